// round 10
// baseline (speedup 1.0000x reference)
#include <cuda_runtime.h>
#include <cuda_fp16.h>
#include <math.h>
#include <stdint.h>

#define B_   4
#define T_   2048
#define DIMN 1024
#define H_   16
#define HD   64
#define MROWS (B_*T_)          // 8192

// ---------------- smem / mma helpers ----------------------------------------
__device__ __forceinline__ uint32_t smem_u32(const void* p) {
    uint32_t a;
    asm("{ .reg .u64 t; cvta.to.shared.u64 t, %1; cvt.u32.u64 %0, t; }"
        : "=r"(a) : "l"(p));
    return a;
}
__device__ __forceinline__ void cp16(uint32_t dst, const void* src) {
    asm volatile("cp.async.cg.shared.global [%0], [%1], 16;"
                 :: "r"(dst), "l"(src) : "memory");
}
#define CP_COMMIT() asm volatile("cp.async.commit_group;" ::: "memory")
#define CP_WAIT(n)  asm volatile("cp.async.wait_group %0;" :: "n"(n) : "memory")

__device__ __forceinline__ void ldsm4(uint32_t* r, uint32_t addr) {
    asm volatile("ldmatrix.sync.aligned.m8n8.x4.shared.b16 {%0,%1,%2,%3}, [%4];"
                 : "=r"(r[0]), "=r"(r[1]), "=r"(r[2]), "=r"(r[3]) : "r"(addr));
}
__device__ __forceinline__ void ldsm4t(uint32_t* r, uint32_t addr) {
    asm volatile("ldmatrix.sync.aligned.m8n8.x4.trans.shared.b16 {%0,%1,%2,%3}, [%4];"
                 : "=r"(r[0]), "=r"(r[1]), "=r"(r[2]), "=r"(r[3]) : "r"(addr));
}
// f16 inputs, f32 accumulate
__device__ __forceinline__ void mma_f32(float* c, const uint32_t* a,
                                        uint32_t b0, uint32_t b1) {
    asm volatile(
        "mma.sync.aligned.m16n8k16.row.col.f32.f16.f16.f32 "
        "{%0,%1,%2,%3}, {%4,%5,%6,%7}, {%8,%9}, {%0,%1,%2,%3};"
        : "+f"(c[0]), "+f"(c[1]), "+f"(c[2]), "+f"(c[3])
        : "r"(a[0]), "r"(a[1]), "r"(a[2]), "r"(a[3]), "r"(b0), "r"(b1));
}
// f16 inputs, f16 accumulate (2 packed regs) — correction terms
__device__ __forceinline__ void mma_f16(uint32_t* c, const uint32_t* a,
                                        uint32_t b0, uint32_t b1) {
    asm volatile(
        "mma.sync.aligned.m16n8k16.row.col.f16.f16.f16.f16 "
        "{%0,%1}, {%2,%3,%4,%5}, {%6,%7}, {%0,%1};"
        : "+r"(c[0]), "+r"(c[1])
        : "r"(a[0]), "r"(a[1]), "r"(a[2]), "r"(a[3]), "r"(b0), "r"(b1));
}
__device__ __forceinline__ uint32_t hbits2(__half2 v) {
    return *reinterpret_cast<uint32_t*>(&v);
}
__device__ __forceinline__ void split_store(__half* hi, __half* lo,
                                            size_t off, float x, float y) {
    __half hx = __float2half_rn(x);
    __half hy = __float2half_rn(y);
    *(__half2*)(hi + off) = __halves2half2(hx, hy);
    *(__half2*)(lo + off) = __halves2half2(
        __float2half_rn(x - __half2float(hx)),
        __float2half_rn(y - __half2float(hy)));
}

// ---------------- scratch (device globals) ----------------------------------
__device__ float g_cos[T_*32];
__device__ float g_sin[T_*32];
__device__ __half g_xhi[3*MROWS*DIMN];
__device__ __half g_xlo[3*MROWS*DIMN];
__device__ __half g_wThi[4*DIMN*DIMN];
__device__ __half g_wTlo[4*DIMN*DIMN];
__device__ __half g_qhi[MROWS*DIMN];
__device__ __half g_qlo[MROWS*DIMN];
__device__ __half g_khi[MROWS*DIMN];
__device__ __half g_klo[MROWS*DIMN];
__device__ __half g_vhi[MROWS*DIMN];
__device__ __half g_vlo[MROWS*DIMN];

// ---------------- RoPE tables -----------------------------------------------
__global__ void rope_tables_kernel() {
    int idx = blockIdx.x * blockDim.x + threadIdx.x;
    if (idx >= T_*32) return;
    int t = idx >> 5;
    int j = idx & 31;
    double inv = pow(10000.0, -(double)(2*j) / 64.0);
    float invf = (float)inv;
    float freq = (float)t * invf;
    g_cos[idx] = (float)cos((double)freq);
    g_sin[idx] = (float)sin((double)freq);
}

// ---------------- batched fp32 -> fp16 hi/lo split (3 activations) ----------
__global__ void convert_act3_kernel(const float* __restrict__ x0,
                                    const float* __restrict__ x1,
                                    const float* __restrict__ x2, int n4) {
    int i = blockIdx.x * blockDim.x + threadIdx.x;
    if (i >= n4) return;
    int z = blockIdx.y;
    const float* x = (z == 0) ? x0 : (z == 1) ? x1 : x2;
    __half2* hp = (__half2*)(g_xhi + (size_t)z * MROWS * DIMN);
    __half2* lp = (__half2*)(g_xlo + (size_t)z * MROWS * DIMN);
    float4 v = ((const float4*)x)[i];
    __half h0 = __float2half_rn(v.x);
    __half h1 = __float2half_rn(v.y);
    __half h2 = __float2half_rn(v.z);
    __half h3 = __float2half_rn(v.w);
    hp[2*i]   = __halves2half2(h0, h1);
    hp[2*i+1] = __halves2half2(h2, h3);
    lp[2*i]   = __halves2half2(__float2half_rn(v.x - __half2float(h0)),
                               __float2half_rn(v.y - __half2float(h1)));
    lp[2*i+1] = __halves2half2(__float2half_rn(v.z - __half2float(h2)),
                               __float2half_rn(v.w - __half2float(h3)));
}

// ---------------- batched fp32 W[k][n] -> fp16 hi/lo transposed (4 weights) -
__global__ void convert_wt4_kernel(const float* __restrict__ W0,
                                   const float* __restrict__ W1,
                                   const float* __restrict__ W2,
                                   const float* __restrict__ W3) {
    __shared__ float t[32][33];
    int z = blockIdx.z;
    const float* W = (z == 0) ? W0 : (z == 1) ? W1 : (z == 2) ? W2 : W3;
    __half* hiT = g_wThi + (size_t)z * DIMN * DIMN;
    __half* loT = g_wTlo + (size_t)z * DIMN * DIMN;
    int tx = threadIdx.x, ty = threadIdx.y;   // 32 x 8
    int n0 = blockIdx.x * 32, k0 = blockIdx.y * 32;
    #pragma unroll
    for (int i = 0; i < 32; i += 8)
        t[ty + i][tx] = W[(size_t)(k0 + ty + i) * DIMN + n0 + tx];
    __syncthreads();
    #pragma unroll
    for (int i = 0; i < 32; i += 8) {
        float x = t[tx][ty + i];
        __half h = __float2half_rn(x);
        size_t o = (size_t)(n0 + ty + i) * DIMN + k0 + tx;
        hiT[o] = h;
        loT[o] = __float2half_rn(x - __half2float(h));
    }
}

// ---------------- batched mma.sync fp16-split GEMM ---------------------------
// main product: f32 accum; correction products: f16 accum (2x rate hypothesis)
#define TK_B   6144
#define STG_B  24576
#define GEMM_SMEM (4*STG_B)   // 98304

struct GemmJob {
    const __half *ahi, *alo, *whT, *wlT;
    const float* bias;
    float* cf;
    __half *chi, *clo;
    float scale;
    int epi;    // 0: fp32 out, 1: split, 2: rope+scale+split
};

__global__ __launch_bounds__(256, 1)
void gemm_tc_kernel(GemmJob j0, GemmJob j1, GemmJob j2) {
    GemmJob jb = (blockIdx.z == 0) ? j0 : (blockIdx.z == 1) ? j1 : j2;
    extern __shared__ char smem[];
    uint32_t sb = smem_u32(smem);
    int tid = threadIdx.x, wid = tid >> 5, lane = tid & 31;
    int m0 = blockIdx.y * 128, n0 = blockIdx.x * 128;

    const __half* srcA_hi = jb.ahi + (size_t)m0 * DIMN;
    const __half* srcA_lo = jb.alo + (size_t)m0 * DIMN;
    const __half* srcW_hi = jb.whT + (size_t)n0 * DIMN;
    const __half* srcW_lo = jb.wlT + (size_t)n0 * DIMN;

    int lr = tid >> 1, lsg = tid & 1;
    uint32_t soff = (uint32_t)lr * 48 + lsg * 16;
    size_t goff = (size_t)lr * DIMN + lsg * 8;

    #define ISSUE(kc) do {                                                    \
        uint32_t _st = sb + ((kc) & 3) * STG_B;                               \
        int _k0 = (kc) * 16;                                                  \
        cp16(_st + 0*TK_B + soff, srcA_hi + _k0 + goff);                      \
        cp16(_st + 1*TK_B + soff, srcA_lo + _k0 + goff);                      \
        cp16(_st + 2*TK_B + soff, srcW_hi + _k0 + goff);                      \
        cp16(_st + 3*TK_B + soff, srcW_lo + _k0 + goff);                      \
    } while (0)

    int m_warp = (wid & 1) * 64;
    int n_warp = (wid >> 1) * 32;
    uint32_t baseA = (uint32_t)(m_warp + (lane & 15)) * 48 + (lane >> 4) * 16;
    uint32_t laneBrow = (lane >> 4) * 8 + (lane & 7);
    uint32_t baseB = (uint32_t)(n_warp + laneBrow) * 48 + ((lane >> 3) & 1) * 16;

    float acc[4][4][4];
    uint32_t accH[4][4][2];
    #pragma unroll
    for (int i = 0; i < 4; i++)
        #pragma unroll
        for (int j = 0; j < 4; j++) {
            #pragma unroll
            for (int q = 0; q < 4; q++) acc[i][j][q] = 0.f;
            accH[i][j][0] = 0u; accH[i][j][1] = 0u;
        }

    ISSUE(0); CP_COMMIT();
    ISSUE(1); CP_COMMIT();
    ISSUE(2); CP_COMMIT();
    ISSUE(3); CP_COMMIT();
    CP_WAIT(2);
    __syncthreads();

    // per k-step: Ah*Wh (f32 acc), Al*Wh (f16 acc), Ah*Wl (f16 acc)
    #define KSTEP(kc) do {                                                    \
        uint32_t st = sb + ((kc) & 3) * STG_B;                                \
        uint32_t A[4][4], AL[4][4], BB[2][4];                                 \
        _Pragma("unroll")                                                     \
        for (int mt = 0; mt < 4; mt++)                                        \
            ldsm4(A[mt], st + baseA + mt * 768);                              \
        _Pragma("unroll")                                                     \
        for (int p = 0; p < 2; p++)                                           \
            ldsm4(BB[p], st + 2*TK_B + baseB + p * 768);                      \
        _Pragma("unroll")                                                     \
        for (int mt = 0; mt < 4; mt++)                                        \
            _Pragma("unroll")                                                 \
            for (int nt = 0; nt < 4; nt++)                                    \
                mma_f32(acc[mt][nt], A[mt],                                   \
                        BB[nt>>1][(nt&1)*2], BB[nt>>1][(nt&1)*2+1]);          \
        _Pragma("unroll")                                                     \
        for (int mt = 0; mt < 4; mt++)                                        \
            ldsm4(AL[mt], st + TK_B + baseA + mt * 768);                      \
        _Pragma("unroll")                                                     \
        for (int mt = 0; mt < 4; mt++)                                        \
            _Pragma("unroll")                                                 \
            for (int nt = 0; nt < 4; nt++)                                    \
                mma_f16(accH[mt][nt], AL[mt],                                 \
                        BB[nt>>1][(nt&1)*2], BB[nt>>1][(nt&1)*2+1]);          \
        _Pragma("unroll")                                                     \
        for (int p = 0; p < 2; p++)                                           \
            ldsm4(BB[p], st + 3*TK_B + baseB + p * 768);                      \
        _Pragma("unroll")                                                     \
        for (int mt = 0; mt < 4; mt++)                                        \
            _Pragma("unroll")                                                 \
            for (int nt = 0; nt < 4; nt++)                                    \
                mma_f16(accH[mt][nt], A[mt],                                  \
                        BB[nt>>1][(nt&1)*2], BB[nt>>1][(nt&1)*2+1]);          \
    } while (0)

    for (int kc = 0; kc < 64; kc += 2) {
        KSTEP(kc);
        KSTEP(kc + 1);
        CP_WAIT(0);
        __syncthreads();
        if (kc + 4 < 64) {
            ISSUE(kc + 4); CP_COMMIT();
            ISSUE(kc + 5); CP_COMMIT();
        }
    }

    int rb = m0 + m_warp + (lane >> 2);
    int cb = n0 + n_warp + (lane & 3) * 2;
    #pragma unroll
    for (int mt = 0; mt < 4; mt++) {
        #pragma unroll
        for (int nt = 0; nt < 4; nt++) {
            int r = rb + mt * 16;
            int c = cb + nt * 8;
            float2 bv = *(const float2*)(jb.bias + c);
            __half2 h0 = *reinterpret_cast<__half2*>(&accH[mt][nt][0]);
            __half2 h1 = *reinterpret_cast<__half2*>(&accH[mt][nt][1]);
            float x0 = acc[mt][nt][0] + __low2float(h0)  + bv.x;
            float y0 = acc[mt][nt][1] + __high2float(h0) + bv.y;
            float x1 = acc[mt][nt][2] + __low2float(h1)  + bv.x;
            float y1 = acc[mt][nt][3] + __high2float(h1) + bv.y;
            if (jb.epi == 0) {
                *(float2*)(jb.cf + (size_t)r * DIMN + c)       = make_float2(x0, y0);
                *(float2*)(jb.cf + (size_t)(r + 8) * DIMN + c) = make_float2(x1, y1);
            } else if (jb.epi == 1) {
                split_store(jb.chi, jb.clo, (size_t)r * DIMN + c, x0, y0);
                split_store(jb.chi, jb.clo, (size_t)(r + 8) * DIMN + c, x1, y1);
            } else {
                int jj = (c & 63) >> 1;
                int t0 = r & (T_ - 1), t1 = (r + 8) & (T_ - 1);
                float c0 = g_cos[t0*32 + jj], s0 = g_sin[t0*32 + jj];
                float c1 = g_cos[t1*32 + jj], s1 = g_sin[t1*32 + jj];
                float rx0 = (x0 * c0 - y0 * s0) * jb.scale;
                float ry0 = (x0 * s0 + y0 * c0) * jb.scale;
                float rx1 = (x1 * c1 - y1 * s1) * jb.scale;
                float ry1 = (x1 * s1 + y1 * c1) * jb.scale;
                split_store(jb.chi, jb.clo, (size_t)r * DIMN + c, rx0, ry0);
                split_store(jb.chi, jb.clo, (size_t)(r + 8) * DIMN + c, rx1, ry1);
            }
        }
    }
    #undef ISSUE
    #undef KSTEP
}

// ---------------- FA2 tensor-core attention (fp16 inputs, f32 accum) --------
#define AT_TILE  9216
#define AT_STAGE 36864
#define ATT_SMEM 73728

__device__ __forceinline__ void load_tile64(uint32_t dst,
                                            const __half* src, int tid) {
    #pragma unroll
    for (int c = 0; c < 4; c++) {
        int chunk = c * 128 + tid;
        int r = chunk >> 3, sg = chunk & 7;
        cp16(dst + r * 144 + sg * 16, src + (size_t)r * DIMN + sg * 8);
    }
}

__global__ __launch_bounds__(128, 3)
void attn_tc_kernel(const __half* __restrict__ qhi_g,
                    const __half* __restrict__ qlo_g,
                    const __half* __restrict__ khi_g,
                    const __half* __restrict__ klo_g,
                    const __half* __restrict__ vhi_g,
                    const __half* __restrict__ vlo_g,
                    __half* __restrict__ Ohi,
                    __half* __restrict__ Olo) {
    extern __shared__ char smem[];
    uint32_t sb = smem_u32(smem);
    int tid = threadIdx.x, wid = tid >> 5, lane = tid & 31;
    int qt = gridDim.x - 1 - blockIdx.x;
    int h = blockIdx.y, b = blockIdx.z;
    int q0 = qt * 64;
    int q0w = q0 + wid * 16;

    size_t hoff = (size_t)h * HD;
    size_t rowbase = (size_t)(b * T_) * DIMN + hoff;
    const __half* qh = qhi_g + rowbase + (size_t)q0 * DIMN;
    const __half* ql = qlo_g + rowbase + (size_t)q0 * DIMN;
    const __half* kh = khi_g + rowbase;
    const __half* kl = klo_g + rowbase;
    const __half* vh = vhi_g + rowbase;
    const __half* vl = vlo_g + rowbase;

    load_tile64(sb,           qh, tid);
    load_tile64(sb + AT_TILE, ql, tid);
    CP_COMMIT();
    CP_WAIT(0);
    __syncthreads();

    uint32_t laneArow = ((lane >> 3) & 1) * 8 + (lane & 7);
    uint32_t qaddr = sb + (wid * 16 + laneArow) * 144 + (lane >> 4) * 16;
    uint32_t qfh[4][4], qfl[4][4];
    #pragma unroll
    for (int ks = 0; ks < 4; ks++) {
        ldsm4(qfh[ks], qaddr + ks * 32);
        ldsm4(qfl[ks], qaddr + AT_TILE + ks * 32);
    }
    __syncthreads();

    int ntile = q0 / 64 + 1;

    {
        uint32_t st = sb;
        load_tile64(st,             kh, tid);
        load_tile64(st + AT_TILE,   kl, tid);
        load_tile64(st + 2*AT_TILE, vh, tid);
        load_tile64(st + 3*AT_TILE, vl, tid);
        CP_COMMIT();
        if (ntile > 1) {
            uint32_t st1 = sb + AT_STAGE;
            const size_t o = (size_t)64 * DIMN;
            load_tile64(st1,             kh + o, tid);
            load_tile64(st1 + AT_TILE,   kl + o, tid);
            load_tile64(st1 + 2*AT_TILE, vh + o, tid);
            load_tile64(st1 + 3*AT_TILE, vl + o, tid);
            CP_COMMIT();
        }
    }

    float oacc[8][4];
    #pragma unroll
    for (int j = 0; j < 8; j++)
        #pragma unroll
        for (int q = 0; q < 4; q++) oacc[j][q] = 0.f;
    float m0 = -1e30f, m1 = -1e30f, l0 = 0.f, l1 = 0.f;

    uint32_t laneBrow = (lane >> 4) * 8 + (lane & 7);
    uint32_t laneBseg = ((lane >> 3) & 1) * 16;
    uint32_t laneVrow = ((lane >> 3) & 1) * 8 + (lane & 7);
    uint32_t laneVseg = (lane >> 4) * 16;

    for (int it = 0; it < ntile; it++) {
        if (it + 1 < ntile) { CP_WAIT(1); } else { CP_WAIT(0); }
        __syncthreads();
        int s0 = it * 64;
        uint32_t st = sb + (it & 1) * AT_STAGE;

        if (s0 <= q0w + 15) {
            float sc[8][4];
            #pragma unroll
            for (int j = 0; j < 8; j++)
                #pragma unroll
                for (int q = 0; q < 4; q++) sc[j][q] = 0.f;

            #pragma unroll
            for (int p = 0; p < 4; p++) {
                uint32_t kaddr = st + (p * 16 + laneBrow) * 144 + laneBseg;
                #pragma unroll
                for (int ks = 0; ks < 4; ks++) {
                    uint32_t bh[4], bl[4];
                    ldsm4(bh, kaddr + ks * 32);
                    ldsm4(bl, kaddr + AT_TILE + ks * 32);
                    mma_f32(sc[2*p],   qfh[ks], bh[0], bh[1]);
                    mma_f32(sc[2*p+1], qfh[ks], bh[2], bh[3]);
                    mma_f32(sc[2*p],   qfl[ks], bh[0], bh[1]);
                    mma_f32(sc[2*p+1], qfl[ks], bh[2], bh[3]);
                    mma_f32(sc[2*p],   qfh[ks], bl[0], bl[1]);
                    mma_f32(sc[2*p+1], qfh[ks], bl[2], bl[3]);
                }
            }

            if (s0 + 63 > q0w) {
                int r0 = q0w + (lane >> 2), r1 = r0 + 8;
                #pragma unroll
                for (int j = 0; j < 8; j++) {
                    int c0 = s0 + j * 8 + (lane & 3) * 2;
                    if (c0     > r0) sc[j][0] = -1e30f;
                    if (c0 + 1 > r0) sc[j][1] = -1e30f;
                    if (c0     > r1) sc[j][2] = -1e30f;
                    if (c0 + 1 > r1) sc[j][3] = -1e30f;
                }
            }

            float mt0 = -1e30f, mt1 = -1e30f;
            #pragma unroll
            for (int j = 0; j < 8; j++) {
                mt0 = fmaxf(mt0, fmaxf(sc[j][0], sc[j][1]));
                mt1 = fmaxf(mt1, fmaxf(sc[j][2], sc[j][3]));
            }
            mt0 = fmaxf(mt0, __shfl_xor_sync(0xffffffffu, mt0, 1));
            mt0 = fmaxf(mt0, __shfl_xor_sync(0xffffffffu, mt0, 2));
            mt1 = fmaxf(mt1, __shfl_xor_sync(0xffffffffu, mt1, 1));
            mt1 = fmaxf(mt1, __shfl_xor_sync(0xffffffffu, mt1, 2));
            float mn0 = fmaxf(m0, mt0), mn1 = fmaxf(m1, mt1);
            float cr0 = __expf(m0 - mn0), cr1 = __expf(m1 - mn1);
            m0 = mn0; m1 = mn1;

            uint32_t phi[16], plo[16];
            float ps0 = 0.f, ps1 = 0.f;
            #pragma unroll
            for (int j = 0; j < 8; j++) {
                float p0 = __expf(sc[j][0] - mn0);
                float p1 = __expf(sc[j][1] - mn0);
                float p2 = __expf(sc[j][2] - mn1);
                float p3 = __expf(sc[j][3] - mn1);
                ps0 += p0 + p1;
                ps1 += p2 + p3;
                __half h0 = __float2half_rn(p0);
                __half h1 = __float2half_rn(p1);
                __half h2 = __float2half_rn(p2);
                __half h3 = __float2half_rn(p3);
                phi[2*j]   = hbits2(__halves2half2(h0, h1));
                phi[2*j+1] = hbits2(__halves2half2(h2, h3));
                plo[2*j]   = hbits2(__halves2half2(
                                 __float2half_rn(p0 - __half2float(h0)),
                                 __float2half_rn(p1 - __half2float(h1))));
                plo[2*j+1] = hbits2(__halves2half2(
                                 __float2half_rn(p2 - __half2float(h2)),
                                 __float2half_rn(p3 - __half2float(h3))));
            }
            ps0 += __shfl_xor_sync(0xffffffffu, ps0, 1);
            ps0 += __shfl_xor_sync(0xffffffffu, ps0, 2);
            ps1 += __shfl_xor_sync(0xffffffffu, ps1, 1);
            ps1 += __shfl_xor_sync(0xffffffffu, ps1, 2);
            l0 = l0 * cr0 + ps0;
            l1 = l1 * cr1 + ps1;

            #pragma unroll
            for (int j = 0; j < 8; j++) {
                oacc[j][0] *= cr0; oacc[j][1] *= cr0;
                oacc[j][2] *= cr1; oacc[j][3] *= cr1;
            }

            #pragma unroll
            for (int dp = 0; dp < 4; dp++) {
                #pragma unroll
                for (int kp = 0; kp < 4; kp++) {
                    uint32_t vaddr = st + 2*AT_TILE +
                        (kp * 16 + laneVrow) * 144 + laneVseg + dp * 32;
                    uint32_t vh4[4], vl4[4];
                    ldsm4t(vh4, vaddr);
                    ldsm4t(vl4, vaddr + AT_TILE);
                    mma_f32(oacc[2*dp],   &phi[4*kp], vh4[0], vh4[1]);
                    mma_f32(oacc[2*dp+1], &phi[4*kp], vh4[2], vh4[3]);
                    mma_f32(oacc[2*dp],   &plo[4*kp], vh4[0], vh4[1]);
                    mma_f32(oacc[2*dp+1], &plo[4*kp], vh4[2], vh4[3]);
                    mma_f32(oacc[2*dp],   &phi[4*kp], vl4[0], vl4[1]);
                    mma_f32(oacc[2*dp+1], &phi[4*kp], vl4[2], vl4[3]);
                }
            }
        }
        __syncthreads();
        if (it + 2 < ntile) {
            uint32_t si = sb + (it & 1) * AT_STAGE;
            const size_t o = (size_t)(it + 2) * 64 * DIMN;
            load_tile64(si,             kh + o, tid);
            load_tile64(si + AT_TILE,   kl + o, tid);
            load_tile64(si + 2*AT_TILE, vh + o, tid);
            load_tile64(si + 3*AT_TILE, vl + o, tid);
            CP_COMMIT();
        }
    }

    float i0 = 1.f / l0, i1 = 1.f / l1;
    size_t r0 = (size_t)(b * T_ + q0w + (lane >> 2)) * DIMN + hoff;
    size_t r1 = r0 + (size_t)8 * DIMN;
    #pragma unroll
    for (int j = 0; j < 8; j++) {
        int col = j * 8 + (lane & 3) * 2;
        split_store(Ohi, Olo, r0 + col, oacc[j][0] * i0, oacc[j][1] * i0);
        split_store(Ohi, Olo, r1 + col, oacc[j][2] * i1, oacc[j][3] * i1);
    }
}

// ---------------- launch ---------------------------------------------------
extern "C" void kernel_launch(void* const* d_in, const int* in_sizes, int n_in,
                              void* d_out, int out_size) {
    const float* query = (const float*)d_in[0];
    const float* key   = (const float*)d_in[1];
    const float* value = (const float*)d_in[2];
    const float* Wq    = (const float*)d_in[3];
    const float* bq    = (const float*)d_in[4];
    const float* Wk    = (const float*)d_in[5];
    const float* bk    = (const float*)d_in[6];
    const float* Wv    = (const float*)d_in[7];
    const float* bv    = (const float*)d_in[8];
    const float* Wo    = (const float*)d_in[9];
    const float* bo    = (const float*)d_in[10];
    float* out = (float*)d_out;

    __half *xhi, *xlo, *wThi, *wTlo;
    __half *qhi, *qlo, *khi, *klo, *vhi, *vlo;
    cudaGetSymbolAddress((void**)&xhi, g_xhi);
    cudaGetSymbolAddress((void**)&xlo, g_xlo);
    cudaGetSymbolAddress((void**)&wThi, g_wThi);
    cudaGetSymbolAddress((void**)&wTlo, g_wTlo);
    cudaGetSymbolAddress((void**)&qhi, g_qhi);
    cudaGetSymbolAddress((void**)&qlo, g_qlo);
    cudaGetSymbolAddress((void**)&khi, g_khi);
    cudaGetSymbolAddress((void**)&klo, g_klo);
    cudaGetSymbolAddress((void**)&vhi, g_vhi);
    cudaGetSymbolAddress((void**)&vlo, g_vlo);

    static bool attr_set = false;
    if (!attr_set) {
        cudaFuncSetAttribute(gemm_tc_kernel,
                             cudaFuncAttributeMaxDynamicSharedMemorySize, GEMM_SMEM);
        cudaFuncSetAttribute(attn_tc_kernel,
                             cudaFuncAttributeMaxDynamicSharedMemorySize, ATT_SMEM);
        attr_set = true;
    }

    const size_t ASZ = (size_t)MROWS * DIMN;
    const size_t WSZ = (size_t)DIMN * DIMN;

    rope_tables_kernel<<<(T_*32 + 255) / 256, 256>>>();

    int n4 = MROWS * DIMN / 4;
    dim3 cvt_grid((n4 + 255) / 256, 3);
    convert_act3_kernel<<<cvt_grid, 256>>>(query, key, value, n4);
    dim3 wt_grid(32, 32, 4), wt_blk(32, 8);
    convert_wt4_kernel<<<wt_grid, wt_blk>>>(Wq, Wk, Wv, Wo);

    GemmJob jq = { xhi,         xlo,         wThi,         wTlo,
                   bq, nullptr, qhi, qlo, 0.125f, 2 };
    GemmJob jk = { xhi + ASZ,   xlo + ASZ,   wThi + WSZ,   wTlo + WSZ,
                   bk, nullptr, khi, klo, 1.0f, 2 };
    GemmJob jv = { xhi + 2*ASZ, xlo + 2*ASZ, wThi + 2*WSZ, wTlo + 2*WSZ,
                   bv, nullptr, vhi, vlo, 1.0f, 1 };
    dim3 qkv_grid(DIMN / 128, MROWS / 128, 3);
    gemm_tc_kernel<<<qkv_grid, 256, GEMM_SMEM>>>(jq, jk, jv);

    dim3 agrid(T_ / 64, H_, B_);
    attn_tc_kernel<<<agrid, 128, ATT_SMEM>>>(qhi, qlo, khi, klo, vhi, vlo,
                                             xhi, xlo);

    GemmJob jo = { xhi, xlo, wThi + 3*WSZ, wTlo + 3*WSZ,
                   bo, out, nullptr, nullptr, 1.0f, 0 };
    dim3 o_grid(DIMN / 128, MROWS / 128, 1);
    gemm_tc_kernel<<<o_grid, 256, GEMM_SMEM>>>(jo, jo, jo);
}

// round 11
// speedup vs baseline: 1.1063x; 1.1063x over previous
#include <cuda_runtime.h>
#include <cuda_fp16.h>
#include <math.h>
#include <stdint.h>

#define B_   4
#define T_   2048
#define DIMN 1024
#define H_   16
#define HD   64
#define MROWS (B_*T_)          // 8192

// ---------------- smem / mma helpers ----------------------------------------
__device__ __forceinline__ uint32_t smem_u32(const void* p) {
    uint32_t a;
    asm("{ .reg .u64 t; cvta.to.shared.u64 t, %1; cvt.u32.u64 %0, t; }"
        : "=r"(a) : "l"(p));
    return a;
}
__device__ __forceinline__ void cp16(uint32_t dst, const void* src) {
    asm volatile("cp.async.cg.shared.global [%0], [%1], 16;"
                 :: "r"(dst), "l"(src) : "memory");
}
#define CP_COMMIT() asm volatile("cp.async.commit_group;" ::: "memory")
#define CP_WAIT(n)  asm volatile("cp.async.wait_group %0;" :: "n"(n) : "memory")

__device__ __forceinline__ void ldsm4(uint32_t* r, uint32_t addr) {
    asm volatile("ldmatrix.sync.aligned.m8n8.x4.shared.b16 {%0,%1,%2,%3}, [%4];"
                 : "=r"(r[0]), "=r"(r[1]), "=r"(r[2]), "=r"(r[3]) : "r"(addr));
}
__device__ __forceinline__ void ldsm4t(uint32_t* r, uint32_t addr) {
    asm volatile("ldmatrix.sync.aligned.m8n8.x4.trans.shared.b16 {%0,%1,%2,%3}, [%4];"
                 : "=r"(r[0]), "=r"(r[1]), "=r"(r[2]), "=r"(r[3]) : "r"(addr));
}
__device__ __forceinline__ void mma_f32(float* c, const uint32_t* a,
                                        uint32_t b0, uint32_t b1) {
    asm volatile(
        "mma.sync.aligned.m16n8k16.row.col.f32.f16.f16.f32 "
        "{%0,%1,%2,%3}, {%4,%5,%6,%7}, {%8,%9}, {%0,%1,%2,%3};"
        : "+f"(c[0]), "+f"(c[1]), "+f"(c[2]), "+f"(c[3])
        : "r"(a[0]), "r"(a[1]), "r"(a[2]), "r"(a[3]), "r"(b0), "r"(b1));
}
__device__ __forceinline__ uint32_t hbits2(__half2 v) {
    return *reinterpret_cast<uint32_t*>(&v);
}
__device__ __forceinline__ void split_store(__half* hi, __half* lo,
                                            size_t off, float x, float y) {
    __half hx = __float2half_rn(x);
    __half hy = __float2half_rn(y);
    *(__half2*)(hi + off) = __halves2half2(hx, hy);
    *(__half2*)(lo + off) = __halves2half2(
        __float2half_rn(x - __half2float(hx)),
        __float2half_rn(y - __half2float(hy)));
}

// ---------------- scratch (device globals) ----------------------------------
__device__ float g_cos[T_*32];
__device__ float g_sin[T_*32];
__device__ __half g_xhi[3*MROWS*DIMN];
__device__ __half g_xlo[3*MROWS*DIMN];
__device__ __half g_wThi[4*DIMN*DIMN];
__device__ __half g_wTlo[4*DIMN*DIMN];
__device__ __half g_qhi[MROWS*DIMN];
__device__ __half g_qlo[MROWS*DIMN];
__device__ __half g_khi[MROWS*DIMN];
__device__ __half g_klo[MROWS*DIMN];
__device__ __half g_vhi[MROWS*DIMN];
__device__ __half g_vlo[MROWS*DIMN];

// ---------------- RoPE tables -----------------------------------------------
__global__ void rope_tables_kernel() {
    int idx = blockIdx.x * blockDim.x + threadIdx.x;
    if (idx >= T_*32) return;
    int t = idx >> 5;
    int j = idx & 31;
    double inv = pow(10000.0, -(double)(2*j) / 64.0);
    float invf = (float)inv;
    float freq = (float)t * invf;
    g_cos[idx] = (float)cos((double)freq);
    g_sin[idx] = (float)sin((double)freq);
}

// ---------------- batched fp32 -> fp16 hi/lo split (3 activations) ----------
__global__ void convert_act3_kernel(const float* __restrict__ x0,
                                    const float* __restrict__ x1,
                                    const float* __restrict__ x2, int n4) {
    int i = blockIdx.x * blockDim.x + threadIdx.x;
    if (i >= n4) return;
    int z = blockIdx.y;
    const float* x = (z == 0) ? x0 : (z == 1) ? x1 : x2;
    __half2* hp = (__half2*)(g_xhi + (size_t)z * MROWS * DIMN);
    __half2* lp = (__half2*)(g_xlo + (size_t)z * MROWS * DIMN);
    float4 v = ((const float4*)x)[i];
    __half h0 = __float2half_rn(v.x);
    __half h1 = __float2half_rn(v.y);
    __half h2 = __float2half_rn(v.z);
    __half h3 = __float2half_rn(v.w);
    hp[2*i]   = __halves2half2(h0, h1);
    hp[2*i+1] = __halves2half2(h2, h3);
    lp[2*i]   = __halves2half2(__float2half_rn(v.x - __half2float(h0)),
                               __float2half_rn(v.y - __half2float(h1)));
    lp[2*i+1] = __halves2half2(__float2half_rn(v.z - __half2float(h2)),
                               __float2half_rn(v.w - __half2float(h3)));
}

// ---------------- batched fp32 W[k][n] -> fp16 hi/lo transposed (4 weights) -
__global__ void convert_wt4_kernel(const float* __restrict__ W0,
                                   const float* __restrict__ W1,
                                   const float* __restrict__ W2,
                                   const float* __restrict__ W3) {
    __shared__ float t[32][33];
    int z = blockIdx.z;
    const float* W = (z == 0) ? W0 : (z == 1) ? W1 : (z == 2) ? W2 : W3;
    __half* hiT = g_wThi + (size_t)z * DIMN * DIMN;
    __half* loT = g_wTlo + (size_t)z * DIMN * DIMN;
    int tx = threadIdx.x, ty = threadIdx.y;   // 32 x 8
    int n0 = blockIdx.x * 32, k0 = blockIdx.y * 32;
    #pragma unroll
    for (int i = 0; i < 32; i += 8)
        t[ty + i][tx] = W[(size_t)(k0 + ty + i) * DIMN + n0 + tx];
    __syncthreads();
    #pragma unroll
    for (int i = 0; i < 32; i += 8) {
        float x = t[tx][ty + i];
        __half h = __float2half_rn(x);
        size_t o = (size_t)(n0 + ty + i) * DIMN + k0 + tx;
        hiT[o] = h;
        loT[o] = __float2half_rn(x - __half2float(h));
    }
}

// ---------------- fp16-split GEMM: 4 warps, 64x64 warp tile ------------------
// CTA 128x128, BK=16, 4 stages; fragment reuse x2 better than 8-warp layout.
#define TK_B   6144
#define STG_B  24576
#define GEMM_SMEM (4*STG_B)   // 98304

struct GemmJob {
    const __half *ahi, *alo, *whT, *wlT;
    const float* bias;
    float* cf;
    __half *chi, *clo;
    float scale;
    int epi;    // 0: fp32 out, 1: split, 2: rope+scale+split
};

__global__ __launch_bounds__(128, 2)
void gemm_tc_kernel(GemmJob j0, GemmJob j1, GemmJob j2) {
    GemmJob jb = (blockIdx.z == 0) ? j0 : (blockIdx.z == 1) ? j1 : j2;
    extern __shared__ char smem[];
    uint32_t sb = smem_u32(smem);
    int tid = threadIdx.x, wid = tid >> 5, lane = tid & 31;
    int m0 = blockIdx.y * 128, n0 = blockIdx.x * 128;

    const __half* srcA_hi = jb.ahi + (size_t)m0 * DIMN;
    const __half* srcA_lo = jb.alo + (size_t)m0 * DIMN;
    const __half* srcW_hi = jb.whT + (size_t)n0 * DIMN;
    const __half* srcW_lo = jb.wlT + (size_t)n0 * DIMN;

    // loader: 128 threads, 2 chunks per tile per thread (rows r, r+64)
    int lr = tid >> 1, lsg = tid & 1;
    uint32_t soff0 = (uint32_t)lr * 48 + lsg * 16;
    uint32_t soff1 = (uint32_t)(lr + 64) * 48 + lsg * 16;
    size_t goff0 = (size_t)lr * DIMN + lsg * 8;
    size_t goff1 = (size_t)(lr + 64) * DIMN + lsg * 8;

    #define ISSUE(kc) do {                                                    \
        uint32_t _st = sb + ((kc) & 3) * STG_B;                               \
        int _k0 = (kc) * 16;                                                  \
        cp16(_st + 0*TK_B + soff0, srcA_hi + _k0 + goff0);                    \
        cp16(_st + 0*TK_B + soff1, srcA_hi + _k0 + goff1);                    \
        cp16(_st + 1*TK_B + soff0, srcA_lo + _k0 + goff0);                    \
        cp16(_st + 1*TK_B + soff1, srcA_lo + _k0 + goff1);                    \
        cp16(_st + 2*TK_B + soff0, srcW_hi + _k0 + goff0);                    \
        cp16(_st + 2*TK_B + soff1, srcW_hi + _k0 + goff1);                    \
        cp16(_st + 3*TK_B + soff0, srcW_lo + _k0 + goff0);                    \
        cp16(_st + 3*TK_B + soff1, srcW_lo + _k0 + goff1);                    \
    } while (0)

    // 2m x 2n warp grid, 64x64 warp tile
    int m_warp = (wid & 1) * 64;
    int n_warp = (wid >> 1) * 64;
    uint32_t baseA = (uint32_t)(m_warp + (lane & 15)) * 48 + (lane >> 4) * 16;
    uint32_t laneBrow = (lane >> 4) * 8 + (lane & 7);
    uint32_t baseB = (uint32_t)(n_warp + laneBrow) * 48 + ((lane >> 3) & 1) * 16;

    float acc[4][8][4];
    #pragma unroll
    for (int i = 0; i < 4; i++)
        #pragma unroll
        for (int j = 0; j < 8; j++)
            #pragma unroll
            for (int q = 0; q < 4; q++) acc[i][j][q] = 0.f;

    ISSUE(0); CP_COMMIT();
    ISSUE(1); CP_COMMIT();
    ISSUE(2); CP_COMMIT();
    ISSUE(3); CP_COMMIT();
    CP_WAIT(2);
    __syncthreads();

    // per k-step: 16 ldsm, 96 mma  (Ah*Wh, Ah*Wl, Al*Wh, all f32 accum)
    #define KSTEP(kc) do {                                                    \
        uint32_t st = sb + ((kc) & 3) * STG_B;                                \
        uint32_t A[4][4], BH[4][4], BL[4][4];                                 \
        _Pragma("unroll")                                                     \
        for (int mt = 0; mt < 4; mt++)                                        \
            ldsm4(A[mt], st + baseA + mt * 768);                              \
        _Pragma("unroll")                                                     \
        for (int nb = 0; nb < 4; nb++)                                        \
            ldsm4(BH[nb], st + 2*TK_B + baseB + nb * 768);                    \
        _Pragma("unroll")                                                     \
        for (int mt = 0; mt < 4; mt++)                                        \
            _Pragma("unroll")                                                 \
            for (int nt = 0; nt < 8; nt++)                                    \
                mma_f32(acc[mt][nt], A[mt],                                   \
                        BH[nt>>1][(nt&1)*2], BH[nt>>1][(nt&1)*2+1]);          \
        _Pragma("unroll")                                                     \
        for (int nb = 0; nb < 4; nb++)                                        \
            ldsm4(BL[nb], st + 3*TK_B + baseB + nb * 768);                    \
        _Pragma("unroll")                                                     \
        for (int mt = 0; mt < 4; mt++)                                        \
            _Pragma("unroll")                                                 \
            for (int nt = 0; nt < 8; nt++)                                    \
                mma_f32(acc[mt][nt], A[mt],                                   \
                        BL[nt>>1][(nt&1)*2], BL[nt>>1][(nt&1)*2+1]);          \
        _Pragma("unroll")                                                     \
        for (int mt = 0; mt < 4; mt++)                                        \
            ldsm4(A[mt], st + TK_B + baseA + mt * 768);                       \
        _Pragma("unroll")                                                     \
        for (int mt = 0; mt < 4; mt++)                                        \
            _Pragma("unroll")                                                 \
            for (int nt = 0; nt < 8; nt++)                                    \
                mma_f32(acc[mt][nt], A[mt],                                   \
                        BH[nt>>1][(nt&1)*2], BH[nt>>1][(nt&1)*2+1]);          \
    } while (0)

    for (int kc = 0; kc < 64; kc += 2) {
        KSTEP(kc);
        KSTEP(kc + 1);
        CP_WAIT(0);
        __syncthreads();
        if (kc + 4 < 64) {
            ISSUE(kc + 4); CP_COMMIT();
            ISSUE(kc + 5); CP_COMMIT();
        }
    }

    int rb = m0 + m_warp + (lane >> 2);
    int cb = n0 + n_warp + (lane & 3) * 2;
    #pragma unroll
    for (int mt = 0; mt < 4; mt++) {
        #pragma unroll
        for (int nt = 0; nt < 8; nt++) {
            int r = rb + mt * 16;
            int c = cb + nt * 8;
            float2 bv = *(const float2*)(jb.bias + c);
            float x0 = acc[mt][nt][0] + bv.x, y0 = acc[mt][nt][1] + bv.y;
            float x1 = acc[mt][nt][2] + bv.x, y1 = acc[mt][nt][3] + bv.y;
            if (jb.epi == 0) {
                *(float2*)(jb.cf + (size_t)r * DIMN + c)       = make_float2(x0, y0);
                *(float2*)(jb.cf + (size_t)(r + 8) * DIMN + c) = make_float2(x1, y1);
            } else if (jb.epi == 1) {
                split_store(jb.chi, jb.clo, (size_t)r * DIMN + c, x0, y0);
                split_store(jb.chi, jb.clo, (size_t)(r + 8) * DIMN + c, x1, y1);
            } else {
                int jj = (c & 63) >> 1;
                int t0 = r & (T_ - 1), t1 = (r + 8) & (T_ - 1);
                float c0 = g_cos[t0*32 + jj], s0 = g_sin[t0*32 + jj];
                float c1 = g_cos[t1*32 + jj], s1 = g_sin[t1*32 + jj];
                float rx0 = (x0 * c0 - y0 * s0) * jb.scale;
                float ry0 = (x0 * s0 + y0 * c0) * jb.scale;
                float rx1 = (x1 * c1 - y1 * s1) * jb.scale;
                float ry1 = (x1 * s1 + y1 * c1) * jb.scale;
                split_store(jb.chi, jb.clo, (size_t)r * DIMN + c, rx0, ry0);
                split_store(jb.chi, jb.clo, (size_t)(r + 8) * DIMN + c, rx1, ry1);
            }
        }
    }
    #undef ISSUE
    #undef KSTEP
}

// ---------------- FA2 tensor-core attention (fp16 inputs, f32 accum) --------
#define AT_TILE  9216
#define AT_STAGE 36864
#define ATT_SMEM 73728

__device__ __forceinline__ void load_tile64(uint32_t dst,
                                            const __half* src, int tid) {
    #pragma unroll
    for (int c = 0; c < 4; c++) {
        int chunk = c * 128 + tid;
        int r = chunk >> 3, sg = chunk & 7;
        cp16(dst + r * 144 + sg * 16, src + (size_t)r * DIMN + sg * 8);
    }
}

__global__ __launch_bounds__(128, 3)
void attn_tc_kernel(const __half* __restrict__ qhi_g,
                    const __half* __restrict__ qlo_g,
                    const __half* __restrict__ khi_g,
                    const __half* __restrict__ klo_g,
                    const __half* __restrict__ vhi_g,
                    const __half* __restrict__ vlo_g,
                    __half* __restrict__ Ohi,
                    __half* __restrict__ Olo) {
    extern __shared__ char smem[];
    uint32_t sb = smem_u32(smem);
    int tid = threadIdx.x, wid = tid >> 5, lane = tid & 31;
    int qt = gridDim.x - 1 - blockIdx.x;
    int h = blockIdx.y, b = blockIdx.z;
    int q0 = qt * 64;
    int q0w = q0 + wid * 16;

    size_t hoff = (size_t)h * HD;
    size_t rowbase = (size_t)(b * T_) * DIMN + hoff;
    const __half* qh = qhi_g + rowbase + (size_t)q0 * DIMN;
    const __half* ql = qlo_g + rowbase + (size_t)q0 * DIMN;
    const __half* kh = khi_g + rowbase;
    const __half* kl = klo_g + rowbase;
    const __half* vh = vhi_g + rowbase;
    const __half* vl = vlo_g + rowbase;

    load_tile64(sb,           qh, tid);
    load_tile64(sb + AT_TILE, ql, tid);
    CP_COMMIT();
    CP_WAIT(0);
    __syncthreads();

    uint32_t laneArow = ((lane >> 3) & 1) * 8 + (lane & 7);
    uint32_t qaddr = sb + (wid * 16 + laneArow) * 144 + (lane >> 4) * 16;
    uint32_t qfh[4][4], qfl[4][4];
    #pragma unroll
    for (int ks = 0; ks < 4; ks++) {
        ldsm4(qfh[ks], qaddr + ks * 32);
        ldsm4(qfl[ks], qaddr + AT_TILE + ks * 32);
    }
    __syncthreads();

    int ntile = q0 / 64 + 1;

    {
        uint32_t st = sb;
        load_tile64(st,             kh, tid);
        load_tile64(st + AT_TILE,   kl, tid);
        load_tile64(st + 2*AT_TILE, vh, tid);
        load_tile64(st + 3*AT_TILE, vl, tid);
        CP_COMMIT();
        if (ntile > 1) {
            uint32_t st1 = sb + AT_STAGE;
            const size_t o = (size_t)64 * DIMN;
            load_tile64(st1,             kh + o, tid);
            load_tile64(st1 + AT_TILE,   kl + o, tid);
            load_tile64(st1 + 2*AT_TILE, vh + o, tid);
            load_tile64(st1 + 3*AT_TILE, vl + o, tid);
            CP_COMMIT();
        }
    }

    float oacc[8][4];
    #pragma unroll
    for (int j = 0; j < 8; j++)
        #pragma unroll
        for (int q = 0; q < 4; q++) oacc[j][q] = 0.f;
    float m0 = -1e30f, m1 = -1e30f, l0 = 0.f, l1 = 0.f;

    uint32_t laneBrow = (lane >> 4) * 8 + (lane & 7);
    uint32_t laneBseg = ((lane >> 3) & 1) * 16;
    uint32_t laneVrow = ((lane >> 3) & 1) * 8 + (lane & 7);
    uint32_t laneVseg = (lane >> 4) * 16;

    for (int it = 0; it < ntile; it++) {
        if (it + 1 < ntile) { CP_WAIT(1); } else { CP_WAIT(0); }
        __syncthreads();
        int s0 = it * 64;
        uint32_t st = sb + (it & 1) * AT_STAGE;

        if (s0 <= q0w + 15) {
            float sc[8][4];
            #pragma unroll
            for (int j = 0; j < 8; j++)
                #pragma unroll
                for (int q = 0; q < 4; q++) sc[j][q] = 0.f;

            #pragma unroll
            for (int p = 0; p < 4; p++) {
                uint32_t kaddr = st + (p * 16 + laneBrow) * 144 + laneBseg;
                #pragma unroll
                for (int ks = 0; ks < 4; ks++) {
                    uint32_t bh[4], bl[4];
                    ldsm4(bh, kaddr + ks * 32);
                    ldsm4(bl, kaddr + AT_TILE + ks * 32);
                    mma_f32(sc[2*p],   qfh[ks], bh[0], bh[1]);
                    mma_f32(sc[2*p+1], qfh[ks], bh[2], bh[3]);
                    mma_f32(sc[2*p],   qfl[ks], bh[0], bh[1]);
                    mma_f32(sc[2*p+1], qfl[ks], bh[2], bh[3]);
                    mma_f32(sc[2*p],   qfh[ks], bl[0], bl[1]);
                    mma_f32(sc[2*p+1], qfh[ks], bl[2], bl[3]);
                }
            }

            if (s0 + 63 > q0w) {
                int r0 = q0w + (lane >> 2), r1 = r0 + 8;
                #pragma unroll
                for (int j = 0; j < 8; j++) {
                    int c0 = s0 + j * 8 + (lane & 3) * 2;
                    if (c0     > r0) sc[j][0] = -1e30f;
                    if (c0 + 1 > r0) sc[j][1] = -1e30f;
                    if (c0     > r1) sc[j][2] = -1e30f;
                    if (c0 + 1 > r1) sc[j][3] = -1e30f;
                }
            }

            float mt0 = -1e30f, mt1 = -1e30f;
            #pragma unroll
            for (int j = 0; j < 8; j++) {
                mt0 = fmaxf(mt0, fmaxf(sc[j][0], sc[j][1]));
                mt1 = fmaxf(mt1, fmaxf(sc[j][2], sc[j][3]));
            }
            mt0 = fmaxf(mt0, __shfl_xor_sync(0xffffffffu, mt0, 1));
            mt0 = fmaxf(mt0, __shfl_xor_sync(0xffffffffu, mt0, 2));
            mt1 = fmaxf(mt1, __shfl_xor_sync(0xffffffffu, mt1, 1));
            mt1 = fmaxf(mt1, __shfl_xor_sync(0xffffffffu, mt1, 2));
            float mn0 = fmaxf(m0, mt0), mn1 = fmaxf(m1, mt1);
            float cr0 = __expf(m0 - mn0), cr1 = __expf(m1 - mn1);
            m0 = mn0; m1 = mn1;

            uint32_t phi[16], plo[16];
            float ps0 = 0.f, ps1 = 0.f;
            #pragma unroll
            for (int j = 0; j < 8; j++) {
                float p0 = __expf(sc[j][0] - mn0);
                float p1 = __expf(sc[j][1] - mn0);
                float p2 = __expf(sc[j][2] - mn1);
                float p3 = __expf(sc[j][3] - mn1);
                ps0 += p0 + p1;
                ps1 += p2 + p3;
                __half h0 = __float2half_rn(p0);
                __half h1 = __float2half_rn(p1);
                __half h2 = __float2half_rn(p2);
                __half h3 = __float2half_rn(p3);
                phi[2*j]   = hbits2(__halves2half2(h0, h1));
                phi[2*j+1] = hbits2(__halves2half2(h2, h3));
                plo[2*j]   = hbits2(__halves2half2(
                                 __float2half_rn(p0 - __half2float(h0)),
                                 __float2half_rn(p1 - __half2float(h1))));
                plo[2*j+1] = hbits2(__halves2half2(
                                 __float2half_rn(p2 - __half2float(h2)),
                                 __float2half_rn(p3 - __half2float(h3))));
            }
            ps0 += __shfl_xor_sync(0xffffffffu, ps0, 1);
            ps0 += __shfl_xor_sync(0xffffffffu, ps0, 2);
            ps1 += __shfl_xor_sync(0xffffffffu, ps1, 1);
            ps1 += __shfl_xor_sync(0xffffffffu, ps1, 2);
            l0 = l0 * cr0 + ps0;
            l1 = l1 * cr1 + ps1;

            #pragma unroll
            for (int j = 0; j < 8; j++) {
                oacc[j][0] *= cr0; oacc[j][1] *= cr0;
                oacc[j][2] *= cr1; oacc[j][3] *= cr1;
            }

            #pragma unroll
            for (int dp = 0; dp < 4; dp++) {
                #pragma unroll
                for (int kp = 0; kp < 4; kp++) {
                    uint32_t vaddr = st + 2*AT_TILE +
                        (kp * 16 + laneVrow) * 144 + laneVseg + dp * 32;
                    uint32_t vh4[4], vl4[4];
                    ldsm4t(vh4, vaddr);
                    ldsm4t(vl4, vaddr + AT_TILE);
                    mma_f32(oacc[2*dp],   &phi[4*kp], vh4[0], vh4[1]);
                    mma_f32(oacc[2*dp+1], &phi[4*kp], vh4[2], vh4[3]);
                    mma_f32(oacc[2*dp],   &plo[4*kp], vh4[0], vh4[1]);
                    mma_f32(oacc[2*dp+1], &plo[4*kp], vh4[2], vh4[3]);
                    mma_f32(oacc[2*dp],   &phi[4*kp], vl4[0], vl4[1]);
                    mma_f32(oacc[2*dp+1], &phi[4*kp], vl4[2], vl4[3]);
                }
            }
        }
        __syncthreads();
        if (it + 2 < ntile) {
            uint32_t si = sb + (it & 1) * AT_STAGE;
            const size_t o = (size_t)(it + 2) * 64 * DIMN;
            load_tile64(si,             kh + o, tid);
            load_tile64(si + AT_TILE,   kl + o, tid);
            load_tile64(si + 2*AT_TILE, vh + o, tid);
            load_tile64(si + 3*AT_TILE, vl + o, tid);
            CP_COMMIT();
        }
    }

    float i0 = 1.f / l0, i1 = 1.f / l1;
    size_t r0 = (size_t)(b * T_ + q0w + (lane >> 2)) * DIMN + hoff;
    size_t r1 = r0 + (size_t)8 * DIMN;
    #pragma unroll
    for (int j = 0; j < 8; j++) {
        int col = j * 8 + (lane & 3) * 2;
        split_store(Ohi, Olo, r0 + col, oacc[j][0] * i0, oacc[j][1] * i0);
        split_store(Ohi, Olo, r1 + col, oacc[j][2] * i1, oacc[j][3] * i1);
    }
}

// ---------------- launch ---------------------------------------------------
extern "C" void kernel_launch(void* const* d_in, const int* in_sizes, int n_in,
                              void* d_out, int out_size) {
    const float* query = (const float*)d_in[0];
    const float* key   = (const float*)d_in[1];
    const float* value = (const float*)d_in[2];
    const float* Wq    = (const float*)d_in[3];
    const float* bq    = (const float*)d_in[4];
    const float* Wk    = (const float*)d_in[5];
    const float* bk    = (const float*)d_in[6];
    const float* Wv    = (const float*)d_in[7];
    const float* bv    = (const float*)d_in[8];
    const float* Wo    = (const float*)d_in[9];
    const float* bo    = (const float*)d_in[10];
    float* out = (float*)d_out;

    __half *xhi, *xlo, *wThi, *wTlo;
    __half *qhi, *qlo, *khi, *klo, *vhi, *vlo;
    cudaGetSymbolAddress((void**)&xhi, g_xhi);
    cudaGetSymbolAddress((void**)&xlo, g_xlo);
    cudaGetSymbolAddress((void**)&wThi, g_wThi);
    cudaGetSymbolAddress((void**)&wTlo, g_wTlo);
    cudaGetSymbolAddress((void**)&qhi, g_qhi);
    cudaGetSymbolAddress((void**)&qlo, g_qlo);
    cudaGetSymbolAddress((void**)&khi, g_khi);
    cudaGetSymbolAddress((void**)&klo, g_klo);
    cudaGetSymbolAddress((void**)&vhi, g_vhi);
    cudaGetSymbolAddress((void**)&vlo, g_vlo);

    static bool attr_set = false;
    if (!attr_set) {
        cudaFuncSetAttribute(gemm_tc_kernel,
                             cudaFuncAttributeMaxDynamicSharedMemorySize, GEMM_SMEM);
        cudaFuncSetAttribute(attn_tc_kernel,
                             cudaFuncAttributeMaxDynamicSharedMemorySize, ATT_SMEM);
        attr_set = true;
    }

    const size_t ASZ = (size_t)MROWS * DIMN;
    const size_t WSZ = (size_t)DIMN * DIMN;

    rope_tables_kernel<<<(T_*32 + 255) / 256, 256>>>();

    int n4 = MROWS * DIMN / 4;
    dim3 cvt_grid((n4 + 255) / 256, 3);
    convert_act3_kernel<<<cvt_grid, 256>>>(query, key, value, n4);
    dim3 wt_grid(32, 32, 4), wt_blk(32, 8);
    convert_wt4_kernel<<<wt_grid, wt_blk>>>(Wq, Wk, Wv, Wo);

    GemmJob jq = { xhi,         xlo,         wThi,         wTlo,
                   bq, nullptr, qhi, qlo, 0.125f, 2 };
    GemmJob jk = { xhi + ASZ,   xlo + ASZ,   wThi + WSZ,   wTlo + WSZ,
                   bk, nullptr, khi, klo, 1.0f, 2 };
    GemmJob jv = { xhi + 2*ASZ, xlo + 2*ASZ, wThi + 2*WSZ, wTlo + 2*WSZ,
                   bv, nullptr, vhi, vlo, 1.0f, 1 };
    dim3 qkv_grid(DIMN / 128, MROWS / 128, 3);
    gemm_tc_kernel<<<qkv_grid, 128, GEMM_SMEM>>>(jq, jk, jv);

    dim3 agrid(T_ / 64, H_, B_);
    attn_tc_kernel<<<agrid, 128, ATT_SMEM>>>(qhi, qlo, khi, klo, vhi, vlo,
                                             xhi, xlo);

    GemmJob jo = { xhi, xlo, wThi + 3*WSZ, wTlo + 3*WSZ,
                   bo, out, nullptr, nullptr, 1.0f, 0 };
    dim3 o_grid(DIMN / 128, MROWS / 128, 1);
    gemm_tc_kernel<<<o_grid, 128, GEMM_SMEM>>>(jo, jo, jo);
}

// round 12
// speedup vs baseline: 1.3887x; 1.2553x over previous
#include <cuda_runtime.h>
#include <cuda_fp16.h>
#include <math.h>
#include <stdint.h>

#define B_   4
#define T_   2048
#define DIMN 1024
#define H_   16
#define HD   64
#define MROWS (B_*T_)          // 8192

// ---------------- smem / mma helpers ----------------------------------------
__device__ __forceinline__ uint32_t smem_u32(const void* p) {
    uint32_t a;
    asm("{ .reg .u64 t; cvta.to.shared.u64 t, %1; cvt.u32.u64 %0, t; }"
        : "=r"(a) : "l"(p));
    return a;
}
__device__ __forceinline__ void cp16(uint32_t dst, const void* src) {
    asm volatile("cp.async.cg.shared.global [%0], [%1], 16;"
                 :: "r"(dst), "l"(src) : "memory");
}
#define CP_COMMIT() asm volatile("cp.async.commit_group;" ::: "memory")
#define CP_WAIT(n)  asm volatile("cp.async.wait_group %0;" :: "n"(n) : "memory")

__device__ __forceinline__ void ldsm4(uint32_t* r, uint32_t addr) {
    asm volatile("ldmatrix.sync.aligned.m8n8.x4.shared.b16 {%0,%1,%2,%3}, [%4];"
                 : "=r"(r[0]), "=r"(r[1]), "=r"(r[2]), "=r"(r[3]) : "r"(addr));
}
__device__ __forceinline__ void ldsm4t(uint32_t* r, uint32_t addr) {
    asm volatile("ldmatrix.sync.aligned.m8n8.x4.trans.shared.b16 {%0,%1,%2,%3}, [%4];"
                 : "=r"(r[0]), "=r"(r[1]), "=r"(r[2]), "=r"(r[3]) : "r"(addr));
}
__device__ __forceinline__ void mma_f32(float* c, const uint32_t* a,
                                        uint32_t b0, uint32_t b1) {
    asm volatile(
        "mma.sync.aligned.m16n8k16.row.col.f32.f16.f16.f32 "
        "{%0,%1,%2,%3}, {%4,%5,%6,%7}, {%8,%9}, {%0,%1,%2,%3};"
        : "+f"(c[0]), "+f"(c[1]), "+f"(c[2]), "+f"(c[3])
        : "r"(a[0]), "r"(a[1]), "r"(a[2]), "r"(a[3]), "r"(b0), "r"(b1));
}
__device__ __forceinline__ uint32_t hbits2(__half2 v) {
    return *reinterpret_cast<uint32_t*>(&v);
}
__device__ __forceinline__ void split_store(__half* hi, __half* lo,
                                            size_t off, float x, float y) {
    __half hx = __float2half_rn(x);
    __half hy = __float2half_rn(y);
    *(__half2*)(hi + off) = __halves2half2(hx, hy);
    *(__half2*)(lo + off) = __halves2half2(
        __float2half_rn(x - __half2float(hx)),
        __float2half_rn(y - __half2float(hy)));
}

// ---------------- scratch (device globals) ----------------------------------
__device__ float g_cos[T_*32];
__device__ float g_sin[T_*32];
__device__ __half g_xhi[3*MROWS*DIMN];
__device__ __half g_xlo[3*MROWS*DIMN];
__device__ __half g_wThi[4*DIMN*DIMN];   // weights: fp16-rounded transposed only
__device__ __half g_qhi[MROWS*DIMN];
__device__ __half g_qlo[MROWS*DIMN];
__device__ __half g_khi[MROWS*DIMN];
__device__ __half g_klo[MROWS*DIMN];
__device__ __half g_vhi[MROWS*DIMN];
__device__ __half g_vlo[MROWS*DIMN];

// ---------------- RoPE tables -----------------------------------------------
__global__ void rope_tables_kernel() {
    int idx = blockIdx.x * blockDim.x + threadIdx.x;
    if (idx >= T_*32) return;
    int t = idx >> 5;
    int j = idx & 31;
    double inv = pow(10000.0, -(double)(2*j) / 64.0);
    float invf = (float)inv;
    float freq = (float)t * invf;
    g_cos[idx] = (float)cos((double)freq);
    g_sin[idx] = (float)sin((double)freq);
}

// ---------------- batched fp32 -> fp16 hi/lo split (3 activations) ----------
__global__ void convert_act3_kernel(const float* __restrict__ x0,
                                    const float* __restrict__ x1,
                                    const float* __restrict__ x2, int n4) {
    int i = blockIdx.x * blockDim.x + threadIdx.x;
    if (i >= n4) return;
    int z = blockIdx.y;
    const float* x = (z == 0) ? x0 : (z == 1) ? x1 : x2;
    __half2* hp = (__half2*)(g_xhi + (size_t)z * MROWS * DIMN);
    __half2* lp = (__half2*)(g_xlo + (size_t)z * MROWS * DIMN);
    float4 v = ((const float4*)x)[i];
    __half h0 = __float2half_rn(v.x);
    __half h1 = __float2half_rn(v.y);
    __half h2 = __float2half_rn(v.z);
    __half h3 = __float2half_rn(v.w);
    hp[2*i]   = __halves2half2(h0, h1);
    hp[2*i+1] = __halves2half2(h2, h3);
    lp[2*i]   = __halves2half2(__float2half_rn(v.x - __half2float(h0)),
                               __float2half_rn(v.y - __half2float(h1)));
    lp[2*i+1] = __halves2half2(__float2half_rn(v.z - __half2float(h2)),
                               __float2half_rn(v.w - __half2float(h3)));
}

// ---------------- batched fp32 W[k][n] -> fp16 transposed [n][k] ------------
__global__ void convert_wt4_kernel(const float* __restrict__ W0,
                                   const float* __restrict__ W1,
                                   const float* __restrict__ W2,
                                   const float* __restrict__ W3) {
    __shared__ float t[32][33];
    int z = blockIdx.z;
    const float* W = (z == 0) ? W0 : (z == 1) ? W1 : (z == 2) ? W2 : W3;
    __half* hiT = g_wThi + (size_t)z * DIMN * DIMN;
    int tx = threadIdx.x, ty = threadIdx.y;   // 32 x 8
    int n0 = blockIdx.x * 32, k0 = blockIdx.y * 32;
    #pragma unroll
    for (int i = 0; i < 32; i += 8)
        t[ty + i][tx] = W[(size_t)(k0 + ty + i) * DIMN + n0 + tx];
    __syncthreads();
    #pragma unroll
    for (int i = 0; i < 32; i += 8) {
        float x = t[tx][ty + i];
        size_t o = (size_t)(n0 + ty + i) * DIMN + k0 + tx;
        hiT[o] = __float2half_rn(x);
    }
}

// ---------------- 2-product fp16-split GEMM ----------------------------------
// C = (Ahi + Alo) @ Whi + bias  (exact in A; error = A @ Wlo ~ 2^-11)
// 128x128 CTA tile, 8 warps (64x32 warp tile), BK=16, 4 stages, 2-kstep barrier.
// stage = 3 tiles (Ahi, Alo, Whi) = 18432 B
#define TK_B   6144
#define STG_B  18432
#define GEMM_SMEM (4*STG_B)   // 73728

struct GemmJob {
    const __half *ahi, *alo, *whT;
    const float* bias;
    float* cf;
    __half *chi, *clo;
    float scale;
    int epi;    // 0: fp32 out, 1: split, 2: rope+scale+split
};

__global__ __launch_bounds__(256, 2)
void gemm_tc_kernel(GemmJob j0, GemmJob j1, GemmJob j2) {
    GemmJob jb = (blockIdx.z == 0) ? j0 : (blockIdx.z == 1) ? j1 : j2;
    extern __shared__ char smem[];
    uint32_t sb = smem_u32(smem);
    int tid = threadIdx.x, wid = tid >> 5, lane = tid & 31;
    int m0 = blockIdx.y * 128, n0 = blockIdx.x * 128;

    const __half* srcA_hi = jb.ahi + (size_t)m0 * DIMN;
    const __half* srcA_lo = jb.alo + (size_t)m0 * DIMN;
    const __half* srcW_hi = jb.whT + (size_t)n0 * DIMN;

    int lr = tid >> 1, lsg = tid & 1;
    uint32_t soff = (uint32_t)lr * 48 + lsg * 16;
    size_t goff = (size_t)lr * DIMN + lsg * 8;

    #define ISSUE(kc) do {                                                    \
        uint32_t _st = sb + ((kc) & 3) * STG_B;                               \
        int _k0 = (kc) * 16;                                                  \
        cp16(_st + 0*TK_B + soff, srcA_hi + _k0 + goff);                      \
        cp16(_st + 1*TK_B + soff, srcA_lo + _k0 + goff);                      \
        cp16(_st + 2*TK_B + soff, srcW_hi + _k0 + goff);                      \
    } while (0)

    int m_warp = (wid & 1) * 64;
    int n_warp = (wid >> 1) * 32;
    uint32_t baseA = (uint32_t)(m_warp + (lane & 15)) * 48 + (lane >> 4) * 16;
    uint32_t laneBrow = (lane >> 4) * 8 + (lane & 7);
    uint32_t baseB = (uint32_t)(n_warp + laneBrow) * 48 + ((lane >> 3) & 1) * 16;

    float acc[4][4][4];
    #pragma unroll
    for (int i = 0; i < 4; i++)
        #pragma unroll
        for (int j = 0; j < 4; j++)
            #pragma unroll
            for (int q = 0; q < 4; q++) acc[i][j][q] = 0.f;

    ISSUE(0); CP_COMMIT();
    ISSUE(1); CP_COMMIT();
    ISSUE(2); CP_COMMIT();
    ISSUE(3); CP_COMMIT();
    CP_WAIT(2);
    __syncthreads();

    // per k-step: 10 ldsm, 32 mma  (Ah*Wh, Al*Wh — both f32 accum)
    #define KSTEP(kc) do {                                                    \
        uint32_t st = sb + ((kc) & 3) * STG_B;                                \
        uint32_t A[4][4], BH[2][4];                                           \
        _Pragma("unroll")                                                     \
        for (int mt = 0; mt < 4; mt++)                                        \
            ldsm4(A[mt], st + baseA + mt * 768);                              \
        _Pragma("unroll")                                                     \
        for (int p = 0; p < 2; p++)                                           \
            ldsm4(BH[p], st + 2*TK_B + baseB + p * 768);                      \
        _Pragma("unroll")                                                     \
        for (int mt = 0; mt < 4; mt++)                                        \
            _Pragma("unroll")                                                 \
            for (int nt = 0; nt < 4; nt++)                                    \
                mma_f32(acc[mt][nt], A[mt],                                   \
                        BH[nt>>1][(nt&1)*2], BH[nt>>1][(nt&1)*2+1]);          \
        _Pragma("unroll")                                                     \
        for (int mt = 0; mt < 4; mt++)                                        \
            ldsm4(A[mt], st + TK_B + baseA + mt * 768);                       \
        _Pragma("unroll")                                                     \
        for (int mt = 0; mt < 4; mt++)                                        \
            _Pragma("unroll")                                                 \
            for (int nt = 0; nt < 4; nt++)                                    \
                mma_f32(acc[mt][nt], A[mt],                                   \
                        BH[nt>>1][(nt&1)*2], BH[nt>>1][(nt&1)*2+1]);          \
    } while (0)

    for (int kc = 0; kc < 64; kc += 2) {
        KSTEP(kc);
        KSTEP(kc + 1);
        CP_WAIT(0);
        __syncthreads();
        if (kc + 4 < 64) {
            ISSUE(kc + 4); CP_COMMIT();
            ISSUE(kc + 5); CP_COMMIT();
        }
    }

    int rb = m0 + m_warp + (lane >> 2);
    int cb = n0 + n_warp + (lane & 3) * 2;
    #pragma unroll
    for (int mt = 0; mt < 4; mt++) {
        #pragma unroll
        for (int nt = 0; nt < 4; nt++) {
            int r = rb + mt * 16;
            int c = cb + nt * 8;
            float2 bv = *(const float2*)(jb.bias + c);
            float x0 = acc[mt][nt][0] + bv.x, y0 = acc[mt][nt][1] + bv.y;
            float x1 = acc[mt][nt][2] + bv.x, y1 = acc[mt][nt][3] + bv.y;
            if (jb.epi == 0) {
                *(float2*)(jb.cf + (size_t)r * DIMN + c)       = make_float2(x0, y0);
                *(float2*)(jb.cf + (size_t)(r + 8) * DIMN + c) = make_float2(x1, y1);
            } else if (jb.epi == 1) {
                split_store(jb.chi, jb.clo, (size_t)r * DIMN + c, x0, y0);
                split_store(jb.chi, jb.clo, (size_t)(r + 8) * DIMN + c, x1, y1);
            } else {
                int jj = (c & 63) >> 1;
                int t0 = r & (T_ - 1), t1 = (r + 8) & (T_ - 1);
                float c0 = g_cos[t0*32 + jj], s0 = g_sin[t0*32 + jj];
                float c1 = g_cos[t1*32 + jj], s1 = g_sin[t1*32 + jj];
                float rx0 = (x0 * c0 - y0 * s0) * jb.scale;
                float ry0 = (x0 * s0 + y0 * c0) * jb.scale;
                float rx1 = (x1 * c1 - y1 * s1) * jb.scale;
                float ry1 = (x1 * s1 + y1 * c1) * jb.scale;
                split_store(jb.chi, jb.clo, (size_t)r * DIMN + c, rx0, ry0);
                split_store(jb.chi, jb.clo, (size_t)(r + 8) * DIMN + c, rx1, ry1);
            }
        }
    }
    #undef ISSUE
    #undef KSTEP
}

// ---------------- FA2 tensor-core attention (fp16, 3-product, unchanged) ----
#define AT_TILE  9216
#define AT_STAGE 36864
#define ATT_SMEM 73728

__device__ __forceinline__ void load_tile64(uint32_t dst,
                                            const __half* src, int tid) {
    #pragma unroll
    for (int c = 0; c < 4; c++) {
        int chunk = c * 128 + tid;
        int r = chunk >> 3, sg = chunk & 7;
        cp16(dst + r * 144 + sg * 16, src + (size_t)r * DIMN + sg * 8);
    }
}

__global__ __launch_bounds__(128, 3)
void attn_tc_kernel(const __half* __restrict__ qhi_g,
                    const __half* __restrict__ qlo_g,
                    const __half* __restrict__ khi_g,
                    const __half* __restrict__ klo_g,
                    const __half* __restrict__ vhi_g,
                    const __half* __restrict__ vlo_g,
                    __half* __restrict__ Ohi,
                    __half* __restrict__ Olo) {
    extern __shared__ char smem[];
    uint32_t sb = smem_u32(smem);
    int tid = threadIdx.x, wid = tid >> 5, lane = tid & 31;
    int qt = gridDim.x - 1 - blockIdx.x;
    int h = blockIdx.y, b = blockIdx.z;
    int q0 = qt * 64;
    int q0w = q0 + wid * 16;

    size_t hoff = (size_t)h * HD;
    size_t rowbase = (size_t)(b * T_) * DIMN + hoff;
    const __half* qh = qhi_g + rowbase + (size_t)q0 * DIMN;
    const __half* ql = qlo_g + rowbase + (size_t)q0 * DIMN;
    const __half* kh = khi_g + rowbase;
    const __half* kl = klo_g + rowbase;
    const __half* vh = vhi_g + rowbase;
    const __half* vl = vlo_g + rowbase;

    load_tile64(sb,           qh, tid);
    load_tile64(sb + AT_TILE, ql, tid);
    CP_COMMIT();
    CP_WAIT(0);
    __syncthreads();

    uint32_t laneArow = ((lane >> 3) & 1) * 8 + (lane & 7);
    uint32_t qaddr = sb + (wid * 16 + laneArow) * 144 + (lane >> 4) * 16;
    uint32_t qfh[4][4], qfl[4][4];
    #pragma unroll
    for (int ks = 0; ks < 4; ks++) {
        ldsm4(qfh[ks], qaddr + ks * 32);
        ldsm4(qfl[ks], qaddr + AT_TILE + ks * 32);
    }
    __syncthreads();

    int ntile = q0 / 64 + 1;

    {
        uint32_t st = sb;
        load_tile64(st,             kh, tid);
        load_tile64(st + AT_TILE,   kl, tid);
        load_tile64(st + 2*AT_TILE, vh, tid);
        load_tile64(st + 3*AT_TILE, vl, tid);
        CP_COMMIT();
        if (ntile > 1) {
            uint32_t st1 = sb + AT_STAGE;
            const size_t o = (size_t)64 * DIMN;
            load_tile64(st1,             kh + o, tid);
            load_tile64(st1 + AT_TILE,   kl + o, tid);
            load_tile64(st1 + 2*AT_TILE, vh + o, tid);
            load_tile64(st1 + 3*AT_TILE, vl + o, tid);
            CP_COMMIT();
        }
    }

    float oacc[8][4];
    #pragma unroll
    for (int j = 0; j < 8; j++)
        #pragma unroll
        for (int q = 0; q < 4; q++) oacc[j][q] = 0.f;
    float m0 = -1e30f, m1 = -1e30f, l0 = 0.f, l1 = 0.f;

    uint32_t laneBrow = (lane >> 4) * 8 + (lane & 7);
    uint32_t laneBseg = ((lane >> 3) & 1) * 16;
    uint32_t laneVrow = ((lane >> 3) & 1) * 8 + (lane & 7);
    uint32_t laneVseg = (lane >> 4) * 16;

    for (int it = 0; it < ntile; it++) {
        if (it + 1 < ntile) { CP_WAIT(1); } else { CP_WAIT(0); }
        __syncthreads();
        int s0 = it * 64;
        uint32_t st = sb + (it & 1) * AT_STAGE;

        if (s0 <= q0w + 15) {
            float sc[8][4];
            #pragma unroll
            for (int j = 0; j < 8; j++)
                #pragma unroll
                for (int q = 0; q < 4; q++) sc[j][q] = 0.f;

            #pragma unroll
            for (int p = 0; p < 4; p++) {
                uint32_t kaddr = st + (p * 16 + laneBrow) * 144 + laneBseg;
                #pragma unroll
                for (int ks = 0; ks < 4; ks++) {
                    uint32_t bh[4], bl[4];
                    ldsm4(bh, kaddr + ks * 32);
                    ldsm4(bl, kaddr + AT_TILE + ks * 32);
                    mma_f32(sc[2*p],   qfh[ks], bh[0], bh[1]);
                    mma_f32(sc[2*p+1], qfh[ks], bh[2], bh[3]);
                    mma_f32(sc[2*p],   qfl[ks], bh[0], bh[1]);
                    mma_f32(sc[2*p+1], qfl[ks], bh[2], bh[3]);
                    mma_f32(sc[2*p],   qfh[ks], bl[0], bl[1]);
                    mma_f32(sc[2*p+1], qfh[ks], bl[2], bl[3]);
                }
            }

            if (s0 + 63 > q0w) {
                int r0 = q0w + (lane >> 2), r1 = r0 + 8;
                #pragma unroll
                for (int j = 0; j < 8; j++) {
                    int c0 = s0 + j * 8 + (lane & 3) * 2;
                    if (c0     > r0) sc[j][0] = -1e30f;
                    if (c0 + 1 > r0) sc[j][1] = -1e30f;
                    if (c0     > r1) sc[j][2] = -1e30f;
                    if (c0 + 1 > r1) sc[j][3] = -1e30f;
                }
            }

            float mt0 = -1e30f, mt1 = -1e30f;
            #pragma unroll
            for (int j = 0; j < 8; j++) {
                mt0 = fmaxf(mt0, fmaxf(sc[j][0], sc[j][1]));
                mt1 = fmaxf(mt1, fmaxf(sc[j][2], sc[j][3]));
            }
            mt0 = fmaxf(mt0, __shfl_xor_sync(0xffffffffu, mt0, 1));
            mt0 = fmaxf(mt0, __shfl_xor_sync(0xffffffffu, mt0, 2));
            mt1 = fmaxf(mt1, __shfl_xor_sync(0xffffffffu, mt1, 1));
            mt1 = fmaxf(mt1, __shfl_xor_sync(0xffffffffu, mt1, 2));
            float mn0 = fmaxf(m0, mt0), mn1 = fmaxf(m1, mt1);
            float cr0 = __expf(m0 - mn0), cr1 = __expf(m1 - mn1);
            m0 = mn0; m1 = mn1;

            uint32_t phi[16], plo[16];
            float ps0 = 0.f, ps1 = 0.f;
            #pragma unroll
            for (int j = 0; j < 8; j++) {
                float p0 = __expf(sc[j][0] - mn0);
                float p1 = __expf(sc[j][1] - mn0);
                float p2 = __expf(sc[j][2] - mn1);
                float p3 = __expf(sc[j][3] - mn1);
                ps0 += p0 + p1;
                ps1 += p2 + p3;
                __half h0 = __float2half_rn(p0);
                __half h1 = __float2half_rn(p1);
                __half h2 = __float2half_rn(p2);
                __half h3 = __float2half_rn(p3);
                phi[2*j]   = hbits2(__halves2half2(h0, h1));
                phi[2*j+1] = hbits2(__halves2half2(h2, h3));
                plo[2*j]   = hbits2(__halves2half2(
                                 __float2half_rn(p0 - __half2float(h0)),
                                 __float2half_rn(p1 - __half2float(h1))));
                plo[2*j+1] = hbits2(__halves2half2(
                                 __float2half_rn(p2 - __half2float(h2)),
                                 __float2half_rn(p3 - __half2float(h3))));
            }
            ps0 += __shfl_xor_sync(0xffffffffu, ps0, 1);
            ps0 += __shfl_xor_sync(0xffffffffu, ps0, 2);
            ps1 += __shfl_xor_sync(0xffffffffu, ps1, 1);
            ps1 += __shfl_xor_sync(0xffffffffu, ps1, 2);
            l0 = l0 * cr0 + ps0;
            l1 = l1 * cr1 + ps1;

            #pragma unroll
            for (int j = 0; j < 8; j++) {
                oacc[j][0] *= cr0; oacc[j][1] *= cr0;
                oacc[j][2] *= cr1; oacc[j][3] *= cr1;
            }

            #pragma unroll
            for (int dp = 0; dp < 4; dp++) {
                #pragma unroll
                for (int kp = 0; kp < 4; kp++) {
                    uint32_t vaddr = st + 2*AT_TILE +
                        (kp * 16 + laneVrow) * 144 + laneVseg + dp * 32;
                    uint32_t vh4[4], vl4[4];
                    ldsm4t(vh4, vaddr);
                    ldsm4t(vl4, vaddr + AT_TILE);
                    mma_f32(oacc[2*dp],   &phi[4*kp], vh4[0], vh4[1]);
                    mma_f32(oacc[2*dp+1], &phi[4*kp], vh4[2], vh4[3]);
                    mma_f32(oacc[2*dp],   &plo[4*kp], vh4[0], vh4[1]);
                    mma_f32(oacc[2*dp+1], &plo[4*kp], vh4[2], vh4[3]);
                    mma_f32(oacc[2*dp],   &phi[4*kp], vl4[0], vl4[1]);
                    mma_f32(oacc[2*dp+1], &phi[4*kp], vl4[2], vl4[3]);
                }
            }
        }
        __syncthreads();
        if (it + 2 < ntile) {
            uint32_t si = sb + (it & 1) * AT_STAGE;
            const size_t o = (size_t)(it + 2) * 64 * DIMN;
            load_tile64(si,             kh + o, tid);
            load_tile64(si + AT_TILE,   kl + o, tid);
            load_tile64(si + 2*AT_TILE, vh + o, tid);
            load_tile64(si + 3*AT_TILE, vl + o, tid);
            CP_COMMIT();
        }
    }

    float i0 = 1.f / l0, i1 = 1.f / l1;
    size_t r0 = (size_t)(b * T_ + q0w + (lane >> 2)) * DIMN + hoff;
    size_t r1 = r0 + (size_t)8 * DIMN;
    #pragma unroll
    for (int j = 0; j < 8; j++) {
        int col = j * 8 + (lane & 3) * 2;
        split_store(Ohi, Olo, r0 + col, oacc[j][0] * i0, oacc[j][1] * i0);
        split_store(Ohi, Olo, r1 + col, oacc[j][2] * i1, oacc[j][3] * i1);
    }
}

// ---------------- launch ---------------------------------------------------
extern "C" void kernel_launch(void* const* d_in, const int* in_sizes, int n_in,
                              void* d_out, int out_size) {
    const float* query = (const float*)d_in[0];
    const float* key   = (const float*)d_in[1];
    const float* value = (const float*)d_in[2];
    const float* Wq    = (const float*)d_in[3];
    const float* bq    = (const float*)d_in[4];
    const float* Wk    = (const float*)d_in[5];
    const float* bk    = (const float*)d_in[6];
    const float* Wv    = (const float*)d_in[7];
    const float* bv    = (const float*)d_in[8];
    const float* Wo    = (const float*)d_in[9];
    const float* bo    = (const float*)d_in[10];
    float* out = (float*)d_out;

    __half *xhi, *xlo, *wThi;
    __half *qhi, *qlo, *khi, *klo, *vhi, *vlo;
    cudaGetSymbolAddress((void**)&xhi, g_xhi);
    cudaGetSymbolAddress((void**)&xlo, g_xlo);
    cudaGetSymbolAddress((void**)&wThi, g_wThi);
    cudaGetSymbolAddress((void**)&qhi, g_qhi);
    cudaGetSymbolAddress((void**)&qlo, g_qlo);
    cudaGetSymbolAddress((void**)&khi, g_khi);
    cudaGetSymbolAddress((void**)&klo, g_klo);
    cudaGetSymbolAddress((void**)&vhi, g_vhi);
    cudaGetSymbolAddress((void**)&vlo, g_vlo);

    static bool attr_set = false;
    if (!attr_set) {
        cudaFuncSetAttribute(gemm_tc_kernel,
                             cudaFuncAttributeMaxDynamicSharedMemorySize, GEMM_SMEM);
        cudaFuncSetAttribute(attn_tc_kernel,
                             cudaFuncAttributeMaxDynamicSharedMemorySize, ATT_SMEM);
        attr_set = true;
    }

    const size_t ASZ = (size_t)MROWS * DIMN;
    const size_t WSZ = (size_t)DIMN * DIMN;

    rope_tables_kernel<<<(T_*32 + 255) / 256, 256>>>();

    int n4 = MROWS * DIMN / 4;
    dim3 cvt_grid((n4 + 255) / 256, 3);
    convert_act3_kernel<<<cvt_grid, 256>>>(query, key, value, n4);
    dim3 wt_grid(32, 32, 4), wt_blk(32, 8);
    convert_wt4_kernel<<<wt_grid, wt_blk>>>(Wq, Wk, Wv, Wo);

    GemmJob jq = { xhi,         xlo,         wThi,
                   bq, nullptr, qhi, qlo, 0.125f, 2 };
    GemmJob jk = { xhi + ASZ,   xlo + ASZ,   wThi + WSZ,
                   bk, nullptr, khi, klo, 1.0f, 2 };
    GemmJob jv = { xhi + 2*ASZ, xlo + 2*ASZ, wThi + 2*WSZ,
                   bv, nullptr, vhi, vlo, 1.0f, 1 };
    dim3 qkv_grid(DIMN / 128, MROWS / 128, 3);
    gemm_tc_kernel<<<qkv_grid, 256, GEMM_SMEM>>>(jq, jk, jv);

    dim3 agrid(T_ / 64, H_, B_);
    attn_tc_kernel<<<agrid, 128, ATT_SMEM>>>(qhi, qlo, khi, klo, vhi, vlo,
                                             xhi, xlo);

    GemmJob jo = { xhi, xlo, wThi + 3*WSZ,
                   bo, out, nullptr, nullptr, 1.0f, 0 };
    dim3 o_grid(DIMN / 128, MROWS / 128, 1);
    gemm_tc_kernel<<<o_grid, 256, GEMM_SMEM>>>(jo, jo, jo);
}

// round 14
// speedup vs baseline: 1.5792x; 1.1372x over previous
#include <cuda_runtime.h>
#include <cuda_fp16.h>
#include <math.h>
#include <stdint.h>

#define B_   4
#define T_   2048
#define DIMN 1024
#define H_   16
#define HD   64
#define MROWS (B_*T_)          // 8192

// ---------------- smem / mma helpers ----------------------------------------
__device__ __forceinline__ uint32_t smem_u32(const void* p) {
    uint32_t a;
    asm("{ .reg .u64 t; cvta.to.shared.u64 t, %1; cvt.u32.u64 %0, t; }"
        : "=r"(a) : "l"(p));
    return a;
}
__device__ __forceinline__ void cp16(uint32_t dst, const void* src) {
    asm volatile("cp.async.cg.shared.global [%0], [%1], 16;"
                 :: "r"(dst), "l"(src) : "memory");
}
#define CP_COMMIT() asm volatile("cp.async.commit_group;" ::: "memory")
#define CP_WAIT(n)  asm volatile("cp.async.wait_group %0;" :: "n"(n) : "memory")

__device__ __forceinline__ void ldsm4(uint32_t* r, uint32_t addr) {
    asm volatile("ldmatrix.sync.aligned.m8n8.x4.shared.b16 {%0,%1,%2,%3}, [%4];"
                 : "=r"(r[0]), "=r"(r[1]), "=r"(r[2]), "=r"(r[3]) : "r"(addr));
}
__device__ __forceinline__ void ldsm4t(uint32_t* r, uint32_t addr) {
    asm volatile("ldmatrix.sync.aligned.m8n8.x4.trans.shared.b16 {%0,%1,%2,%3}, [%4];"
                 : "=r"(r[0]), "=r"(r[1]), "=r"(r[2]), "=r"(r[3]) : "r"(addr));
}
__device__ __forceinline__ void mma_f32(float* c, const uint32_t* a,
                                        uint32_t b0, uint32_t b1) {
    asm volatile(
        "mma.sync.aligned.m16n8k16.row.col.f32.f16.f16.f32 "
        "{%0,%1,%2,%3}, {%4,%5,%6,%7}, {%8,%9}, {%0,%1,%2,%3};"
        : "+f"(c[0]), "+f"(c[1]), "+f"(c[2]), "+f"(c[3])
        : "r"(a[0]), "r"(a[1]), "r"(a[2]), "r"(a[3]), "r"(b0), "r"(b1));
}
__device__ __forceinline__ uint32_t hbits2(__half2 v) {
    return *reinterpret_cast<uint32_t*>(&v);
}
__device__ __forceinline__ void split_store(__half* hi, __half* lo,
                                            size_t off, float x, float y) {
    __half hx = __float2half_rn(x);
    __half hy = __float2half_rn(y);
    *(__half2*)(hi + off) = __halves2half2(hx, hy);
    if (lo)
        *(__half2*)(lo + off) = __halves2half2(
            __float2half_rn(x - __half2float(hx)),
            __float2half_rn(y - __half2float(hy)));
}

// ---------------- scratch (device globals) ----------------------------------
__device__ float g_cos[T_*32];
__device__ float g_sin[T_*32];
__device__ __half g_xhi[3*MROWS*DIMN];
__device__ __half g_xlo[3*MROWS*DIMN];
__device__ __half g_wThi[4*DIMN*DIMN];
__device__ __half g_qhi[MROWS*DIMN];
__device__ __half g_qlo[MROWS*DIMN];
__device__ __half g_khi[MROWS*DIMN];
__device__ __half g_vhi[MROWS*DIMN];

// ---------------- RoPE tables -----------------------------------------------
__global__ void rope_tables_kernel() {
    int idx = blockIdx.x * blockDim.x + threadIdx.x;
    if (idx >= T_*32) return;
    int t = idx >> 5;
    int j = idx & 31;
    double inv = pow(10000.0, -(double)(2*j) / 64.0);
    float invf = (float)inv;
    float freq = (float)t * invf;
    g_cos[idx] = (float)cos((double)freq);
    g_sin[idx] = (float)sin((double)freq);
}

// ---------------- batched fp32 -> fp16 hi/lo split (3 activations) ----------
__global__ void convert_act3_kernel(const float* __restrict__ x0,
                                    const float* __restrict__ x1,
                                    const float* __restrict__ x2, int n4) {
    int i = blockIdx.x * blockDim.x + threadIdx.x;
    if (i >= n4) return;
    int z = blockIdx.y;
    const float* x = (z == 0) ? x0 : (z == 1) ? x1 : x2;
    __half2* hp = (__half2*)(g_xhi + (size_t)z * MROWS * DIMN);
    __half2* lp = (__half2*)(g_xlo + (size_t)z * MROWS * DIMN);
    float4 v = ((const float4*)x)[i];
    __half h0 = __float2half_rn(v.x);
    __half h1 = __float2half_rn(v.y);
    __half h2 = __float2half_rn(v.z);
    __half h3 = __float2half_rn(v.w);
    hp[2*i]   = __halves2half2(h0, h1);
    hp[2*i+1] = __halves2half2(h2, h3);
    lp[2*i]   = __halves2half2(__float2half_rn(v.x - __half2float(h0)),
                               __float2half_rn(v.y - __half2float(h1)));
    lp[2*i+1] = __halves2half2(__float2half_rn(v.z - __half2float(h2)),
                               __float2half_rn(v.w - __half2float(h3)));
}

// ---------------- batched fp32 W[k][n] -> fp16 transposed [n][k] ------------
__global__ void convert_wt4_kernel(const float* __restrict__ W0,
                                   const float* __restrict__ W1,
                                   const float* __restrict__ W2,
                                   const float* __restrict__ W3) {
    __shared__ float t[32][33];
    int z = blockIdx.z;
    const float* W = (z == 0) ? W0 : (z == 1) ? W1 : (z == 2) ? W2 : W3;
    __half* hiT = g_wThi + (size_t)z * DIMN * DIMN;
    int tx = threadIdx.x, ty = threadIdx.y;   // 32 x 8
    int n0 = blockIdx.x * 32, k0 = blockIdx.y * 32;
    #pragma unroll
    for (int i = 0; i < 32; i += 8)
        t[ty + i][tx] = W[(size_t)(k0 + ty + i) * DIMN + n0 + tx];
    __syncthreads();
    #pragma unroll
    for (int i = 0; i < 32; i += 8) {
        float x = t[tx][ty + i];
        size_t o = (size_t)(n0 + ty + i) * DIMN + k0 + tx;
        hiT[o] = __float2half_rn(x);
    }
}

// ---------------- 2-product fp16-split GEMM (R12, unchanged core) -----------
#define TK_B   6144
#define STG_B  18432
#define GEMM_SMEM (4*STG_B)   // 73728

struct GemmJob {
    const __half *ahi, *alo, *whT;
    const float* bias;
    float* cf;
    __half *chi, *clo;    // clo may be nullptr (hi-only store)
    float scale;
    int epi;    // 0: fp32 out, 1: split, 2: rope+scale+split
};

__global__ __launch_bounds__(256, 2)
void gemm_tc_kernel(GemmJob j0, GemmJob j1, GemmJob j2) {
    GemmJob jb = (blockIdx.z == 0) ? j0 : (blockIdx.z == 1) ? j1 : j2;
    extern __shared__ char smem[];
    uint32_t sb = smem_u32(smem);
    int tid = threadIdx.x, wid = tid >> 5, lane = tid & 31;
    int m0 = blockIdx.y * 128, n0 = blockIdx.x * 128;

    const __half* srcA_hi = jb.ahi + (size_t)m0 * DIMN;
    const __half* srcA_lo = jb.alo + (size_t)m0 * DIMN;
    const __half* srcW_hi = jb.whT + (size_t)n0 * DIMN;

    int lr = tid >> 1, lsg = tid & 1;
    uint32_t soff = (uint32_t)lr * 48 + lsg * 16;
    size_t goff = (size_t)lr * DIMN + lsg * 8;

    #define ISSUE(kc) do {                                                    \
        uint32_t _st = sb + ((kc) & 3) * STG_B;                               \
        int _k0 = (kc) * 16;                                                  \
        cp16(_st + 0*TK_B + soff, srcA_hi + _k0 + goff);                      \
        cp16(_st + 1*TK_B + soff, srcA_lo + _k0 + goff);                      \
        cp16(_st + 2*TK_B + soff, srcW_hi + _k0 + goff);                      \
    } while (0)

    int m_warp = (wid & 1) * 64;
    int n_warp = (wid >> 1) * 32;
    uint32_t baseA = (uint32_t)(m_warp + (lane & 15)) * 48 + (lane >> 4) * 16;
    uint32_t laneBrow = (lane >> 4) * 8 + (lane & 7);
    uint32_t baseB = (uint32_t)(n_warp + laneBrow) * 48 + ((lane >> 3) & 1) * 16;

    float acc[4][4][4];
    #pragma unroll
    for (int i = 0; i < 4; i++)
        #pragma unroll
        for (int j = 0; j < 4; j++)
            #pragma unroll
            for (int q = 0; q < 4; q++) acc[i][j][q] = 0.f;

    ISSUE(0); CP_COMMIT();
    ISSUE(1); CP_COMMIT();
    ISSUE(2); CP_COMMIT();
    ISSUE(3); CP_COMMIT();
    CP_WAIT(2);
    __syncthreads();

    #define KSTEP(kc) do {                                                    \
        uint32_t st = sb + ((kc) & 3) * STG_B;                                \
        uint32_t A[4][4], BH[2][4];                                           \
        _Pragma("unroll")                                                     \
        for (int mt = 0; mt < 4; mt++)                                        \
            ldsm4(A[mt], st + baseA + mt * 768);                              \
        _Pragma("unroll")                                                     \
        for (int p = 0; p < 2; p++)                                           \
            ldsm4(BH[p], st + 2*TK_B + baseB + p * 768);                      \
        _Pragma("unroll")                                                     \
        for (int mt = 0; mt < 4; mt++)                                        \
            _Pragma("unroll")                                                 \
            for (int nt = 0; nt < 4; nt++)                                    \
                mma_f32(acc[mt][nt], A[mt],                                   \
                        BH[nt>>1][(nt&1)*2], BH[nt>>1][(nt&1)*2+1]);          \
        _Pragma("unroll")                                                     \
        for (int mt = 0; mt < 4; mt++)                                        \
            ldsm4(A[mt], st + TK_B + baseA + mt * 768);                       \
        _Pragma("unroll")                                                     \
        for (int mt = 0; mt < 4; mt++)                                        \
            _Pragma("unroll")                                                 \
            for (int nt = 0; nt < 4; nt++)                                    \
                mma_f32(acc[mt][nt], A[mt],                                   \
                        BH[nt>>1][(nt&1)*2], BH[nt>>1][(nt&1)*2+1]);          \
    } while (0)

    for (int kc = 0; kc < 64; kc += 2) {
        KSTEP(kc);
        KSTEP(kc + 1);
        CP_WAIT(0);
        __syncthreads();
        if (kc + 4 < 64) {
            ISSUE(kc + 4); CP_COMMIT();
            ISSUE(kc + 5); CP_COMMIT();
        }
    }

    int rb = m0 + m_warp + (lane >> 2);
    int cb = n0 + n_warp + (lane & 3) * 2;
    #pragma unroll
    for (int mt = 0; mt < 4; mt++) {
        #pragma unroll
        for (int nt = 0; nt < 4; nt++) {
            int r = rb + mt * 16;
            int c = cb + nt * 8;
            float2 bv = *(const float2*)(jb.bias + c);
            float x0 = acc[mt][nt][0] + bv.x, y0 = acc[mt][nt][1] + bv.y;
            float x1 = acc[mt][nt][2] + bv.x, y1 = acc[mt][nt][3] + bv.y;
            if (jb.epi == 0) {
                *(float2*)(jb.cf + (size_t)r * DIMN + c)       = make_float2(x0, y0);
                *(float2*)(jb.cf + (size_t)(r + 8) * DIMN + c) = make_float2(x1, y1);
            } else if (jb.epi == 1) {
                split_store(jb.chi, jb.clo, (size_t)r * DIMN + c, x0, y0);
                split_store(jb.chi, jb.clo, (size_t)(r + 8) * DIMN + c, x1, y1);
            } else {
                int jj = (c & 63) >> 1;
                int t0 = r & (T_ - 1), t1 = (r + 8) & (T_ - 1);
                float c0 = g_cos[t0*32 + jj], s0 = g_sin[t0*32 + jj];
                float c1 = g_cos[t1*32 + jj], s1 = g_sin[t1*32 + jj];
                float rx0 = (x0 * c0 - y0 * s0) * jb.scale;
                float ry0 = (x0 * s0 + y0 * c0) * jb.scale;
                float rx1 = (x1 * c1 - y1 * s1) * jb.scale;
                float ry1 = (x1 * s1 + y1 * c1) * jb.scale;
                split_store(jb.chi, jb.clo, (size_t)r * DIMN + c, rx0, ry0);
                split_store(jb.chi, jb.clo, (size_t)(r + 8) * DIMN + c, rx1, ry1);
            }
        }
    }
    #undef ISSUE
    #undef KSTEP
}

// ---------------- FA2 attention: 2-product QK and PV ------------------------
// QK = (qhi+qlo)·khi ; PV = (phi+plo)·vhi. K/V lo tiles eliminated.
#define AT_TILE  9216
#define AT_STAGE 18432          // khi + vhi
#define ATT_SMEM 36864          // 2 stages

__device__ __forceinline__ void load_tile64(uint32_t dst,
                                            const __half* src, int tid) {
    #pragma unroll
    for (int c = 0; c < 4; c++) {
        int chunk = c * 128 + tid;
        int r = chunk >> 3, sg = chunk & 7;
        cp16(dst + r * 144 + sg * 16, src + (size_t)r * DIMN + sg * 8);
    }
}

__global__ __launch_bounds__(128, 3)
void attn_tc_kernel(const __half* __restrict__ qhi_g,
                    const __half* __restrict__ qlo_g,
                    const __half* __restrict__ khi_g,
                    const __half* __restrict__ vhi_g,
                    __half* __restrict__ Ohi,
                    __half* __restrict__ Olo) {
    extern __shared__ char smem[];
    uint32_t sb = smem_u32(smem);
    int tid = threadIdx.x, wid = tid >> 5, lane = tid & 31;
    int qt = gridDim.x - 1 - blockIdx.x;
    int h = blockIdx.y, b = blockIdx.z;
    int q0 = qt * 64;
    int q0w = q0 + wid * 16;

    size_t hoff = (size_t)h * HD;
    size_t rowbase = (size_t)(b * T_) * DIMN + hoff;
    const __half* qh = qhi_g + rowbase + (size_t)q0 * DIMN;
    const __half* ql = qlo_g + rowbase + (size_t)q0 * DIMN;
    const __half* kh = khi_g + rowbase;
    const __half* vh = vhi_g + rowbase;

    // stage Q (hi,lo) into smem, build fragments
    load_tile64(sb,           qh, tid);
    load_tile64(sb + AT_TILE, ql, tid);
    CP_COMMIT();
    CP_WAIT(0);
    __syncthreads();

    uint32_t laneArow = ((lane >> 3) & 1) * 8 + (lane & 7);
    uint32_t qaddr = sb + (wid * 16 + laneArow) * 144 + (lane >> 4) * 16;
    uint32_t qfh[4][4], qfl[4][4];
    #pragma unroll
    for (int ks = 0; ks < 4; ks++) {
        ldsm4(qfh[ks], qaddr + ks * 32);
        ldsm4(qfl[ks], qaddr + AT_TILE + ks * 32);
    }
    __syncthreads();

    int ntile = q0 / 64 + 1;

    {
        load_tile64(sb,           kh, tid);
        load_tile64(sb + AT_TILE, vh, tid);
        CP_COMMIT();
        if (ntile > 1) {
            const size_t o = (size_t)64 * DIMN;
            load_tile64(sb + AT_STAGE,           kh + o, tid);
            load_tile64(sb + AT_STAGE + AT_TILE, vh + o, tid);
            CP_COMMIT();
        }
    }

    float oacc[8][4];
    #pragma unroll
    for (int j = 0; j < 8; j++)
        #pragma unroll
        for (int q = 0; q < 4; q++) oacc[j][q] = 0.f;
    float m0 = -1e30f, m1 = -1e30f, l0 = 0.f, l1 = 0.f;

    uint32_t laneBrow = (lane >> 4) * 8 + (lane & 7);
    uint32_t laneBseg = ((lane >> 3) & 1) * 16;
    uint32_t laneVrow = ((lane >> 3) & 1) * 8 + (lane & 7);
    uint32_t laneVseg = (lane >> 4) * 16;

    for (int it = 0; it < ntile; it++) {
        if (it + 1 < ntile) { CP_WAIT(1); } else { CP_WAIT(0); }
        __syncthreads();
        int s0 = it * 64;
        uint32_t st = sb + (it & 1) * AT_STAGE;

        if (s0 <= q0w + 15) {
            float sc[8][4];
            #pragma unroll
            for (int j = 0; j < 8; j++)
                #pragma unroll
                for (int q = 0; q < 4; q++) sc[j][q] = 0.f;

            // ---- S = (Qhi + Qlo) Khi^T ----
            #pragma unroll
            for (int p = 0; p < 4; p++) {
                uint32_t kaddr = st + (p * 16 + laneBrow) * 144 + laneBseg;
                #pragma unroll
                for (int ks = 0; ks < 4; ks++) {
                    uint32_t bh[4];
                    ldsm4(bh, kaddr + ks * 32);
                    mma_f32(sc[2*p],   qfh[ks], bh[0], bh[1]);
                    mma_f32(sc[2*p+1], qfh[ks], bh[2], bh[3]);
                    mma_f32(sc[2*p],   qfl[ks], bh[0], bh[1]);
                    mma_f32(sc[2*p+1], qfl[ks], bh[2], bh[3]);
                }
            }

            if (s0 + 63 > q0w) {
                int r0 = q0w + (lane >> 2), r1 = r0 + 8;
                #pragma unroll
                for (int j = 0; j < 8; j++) {
                    int c0 = s0 + j * 8 + (lane & 3) * 2;
                    if (c0     > r0) sc[j][0] = -1e30f;
                    if (c0 + 1 > r0) sc[j][1] = -1e30f;
                    if (c0     > r1) sc[j][2] = -1e30f;
                    if (c0 + 1 > r1) sc[j][3] = -1e30f;
                }
            }

            float mt0 = -1e30f, mt1 = -1e30f;
            #pragma unroll
            for (int j = 0; j < 8; j++) {
                mt0 = fmaxf(mt0, fmaxf(sc[j][0], sc[j][1]));
                mt1 = fmaxf(mt1, fmaxf(sc[j][2], sc[j][3]));
            }
            mt0 = fmaxf(mt0, __shfl_xor_sync(0xffffffffu, mt0, 1));
            mt0 = fmaxf(mt0, __shfl_xor_sync(0xffffffffu, mt0, 2));
            mt1 = fmaxf(mt1, __shfl_xor_sync(0xffffffffu, mt1, 1));
            mt1 = fmaxf(mt1, __shfl_xor_sync(0xffffffffu, mt1, 2));
            float mn0 = fmaxf(m0, mt0), mn1 = fmaxf(m1, mt1);
            float cr0 = __expf(m0 - mn0), cr1 = __expf(m1 - mn1);
            m0 = mn0; m1 = mn1;

            uint32_t phi[16], plo[16];
            float ps0 = 0.f, ps1 = 0.f;
            #pragma unroll
            for (int j = 0; j < 8; j++) {
                float p0 = __expf(sc[j][0] - mn0);
                float p1 = __expf(sc[j][1] - mn0);
                float p2 = __expf(sc[j][2] - mn1);
                float p3 = __expf(sc[j][3] - mn1);
                ps0 += p0 + p1;
                ps1 += p2 + p3;
                __half h0 = __float2half_rn(p0);
                __half h1 = __float2half_rn(p1);
                __half h2 = __float2half_rn(p2);
                __half h3 = __float2half_rn(p3);
                phi[2*j]   = hbits2(__halves2half2(h0, h1));
                phi[2*j+1] = hbits2(__halves2half2(h2, h3));
                plo[2*j]   = hbits2(__halves2half2(
                                 __float2half_rn(p0 - __half2float(h0)),
                                 __float2half_rn(p1 - __half2float(h1))));
                plo[2*j+1] = hbits2(__halves2half2(
                                 __float2half_rn(p2 - __half2float(h2)),
                                 __float2half_rn(p3 - __half2float(h3))));
            }
            ps0 += __shfl_xor_sync(0xffffffffu, ps0, 1);
            ps0 += __shfl_xor_sync(0xffffffffu, ps0, 2);
            ps1 += __shfl_xor_sync(0xffffffffu, ps1, 1);
            ps1 += __shfl_xor_sync(0xffffffffu, ps1, 2);
            l0 = l0 * cr0 + ps0;
            l1 = l1 * cr1 + ps1;

            #pragma unroll
            for (int j = 0; j < 8; j++) {
                oacc[j][0] *= cr0; oacc[j][1] *= cr0;
                oacc[j][2] *= cr1; oacc[j][3] *= cr1;
            }

            // ---- O += (Phi + Plo) Vhi ----
            #pragma unroll
            for (int dp = 0; dp < 4; dp++) {
                #pragma unroll
                for (int kp = 0; kp < 4; kp++) {
                    uint32_t vaddr = st + AT_TILE +
                        (kp * 16 + laneVrow) * 144 + laneVseg + dp * 32;
                    uint32_t vh4[4];
                    ldsm4t(vh4, vaddr);
                    mma_f32(oacc[2*dp],   &phi[4*kp], vh4[0], vh4[1]);
                    mma_f32(oacc[2*dp+1], &phi[4*kp], vh4[2], vh4[3]);
                    mma_f32(oacc[2*dp],   &plo[4*kp], vh4[0], vh4[1]);
                    mma_f32(oacc[2*dp+1], &plo[4*kp], vh4[2], vh4[3]);
                }
            }
        }
        __syncthreads();
        if (it + 2 < ntile) {
            uint32_t si = sb + (it & 1) * AT_STAGE;
            const size_t o = (size_t)(it + 2) * 64 * DIMN;
            load_tile64(si,           kh + o, tid);
            load_tile64(si + AT_TILE, vh + o, tid);
            CP_COMMIT();
        }
    }

    float i0 = 1.f / l0, i1 = 1.f / l1;
    size_t r0 = (size_t)(b * T_ + q0w + (lane >> 2)) * DIMN + hoff;
    size_t r1 = r0 + (size_t)8 * DIMN;
    #pragma unroll
    for (int j = 0; j < 8; j++) {
        int col = j * 8 + (lane & 3) * 2;
        split_store(Ohi, Olo, r0 + col, oacc[j][0] * i0, oacc[j][1] * i0);
        split_store(Ohi, Olo, r1 + col, oacc[j][2] * i1, oacc[j][3] * i1);
    }
}

// ---------------- launch ---------------------------------------------------
extern "C" void kernel_launch(void* const* d_in, const int* in_sizes, int n_in,
                              void* d_out, int out_size) {
    const float* query = (const float*)d_in[0];
    const float* key   = (const float*)d_in[1];
    const float* value = (const float*)d_in[2];
    const float* Wq    = (const float*)d_in[3];
    const float* bq    = (const float*)d_in[4];
    const float* Wk    = (const float*)d_in[5];
    const float* bk    = (const float*)d_in[6];
    const float* Wv    = (const float*)d_in[7];
    const float* bv    = (const float*)d_in[8];
    const float* Wo    = (const float*)d_in[9];
    const float* bo    = (const float*)d_in[10];
    float* out = (float*)d_out;

    __half *xhi, *xlo, *wThi;
    __half *qhi, *qlo, *khi, *vhi;
    cudaGetSymbolAddress((void**)&xhi, g_xhi);
    cudaGetSymbolAddress((void**)&xlo, g_xlo);
    cudaGetSymbolAddress((void**)&wThi, g_wThi);
    cudaGetSymbolAddress((void**)&qhi, g_qhi);
    cudaGetSymbolAddress((void**)&qlo, g_qlo);
    cudaGetSymbolAddress((void**)&khi, g_khi);
    cudaGetSymbolAddress((void**)&vhi, g_vhi);

    static bool attr_set = false;
    if (!attr_set) {
        cudaFuncSetAttribute(gemm_tc_kernel,
                             cudaFuncAttributeMaxDynamicSharedMemorySize, GEMM_SMEM);
        cudaFuncSetAttribute(attn_tc_kernel,
                             cudaFuncAttributeMaxDynamicSharedMemorySize, ATT_SMEM);
        attr_set = true;
    }

    const size_t ASZ = (size_t)MROWS * DIMN;
    const size_t WSZ = (size_t)DIMN * DIMN;

    rope_tables_kernel<<<(T_*32 + 255) / 256, 256>>>();

    int n4 = MROWS * DIMN / 4;
    dim3 cvt_grid((n4 + 255) / 256, 3);
    convert_act3_kernel<<<cvt_grid, 256>>>(query, key, value, n4);
    dim3 wt_grid(32, 32, 4), wt_blk(32, 8);
    convert_wt4_kernel<<<wt_grid, wt_blk>>>(Wq, Wk, Wv, Wo);

    GemmJob jq = { xhi,         xlo,         wThi,
                   bq, nullptr, qhi, qlo, 0.125f, 2 };
    GemmJob jk = { xhi + ASZ,   xlo + ASZ,   wThi + WSZ,
                   bk, nullptr, khi, nullptr, 1.0f, 2 };
    GemmJob jv = { xhi + 2*ASZ, xlo + 2*ASZ, wThi + 2*WSZ,
                   bv, nullptr, vhi, nullptr, 1.0f, 1 };
    dim3 qkv_grid(DIMN / 128, MROWS / 128, 3);
    gemm_tc_kernel<<<qkv_grid, 256, GEMM_SMEM>>>(jq, jk, jv);

    dim3 agrid(T_ / 64, H_, B_);
    attn_tc_kernel<<<agrid, 128, ATT_SMEM>>>(qhi, qlo, khi, vhi, xhi, xlo);

    GemmJob jo = { xhi, xlo, wThi + 3*WSZ,
                   bo, out, nullptr, nullptr, 1.0f, 0 };
    dim3 o_grid(DIMN / 128, MROWS / 128, 1);
    gemm_tc_kernel<<<o_grid, 256, GEMM_SMEM>>>(jo, jo, jo);
}